// round 14
// baseline (speedup 1.0000x reference)
#include <cuda_runtime.h>
#include <cuda_fp16.h>
#include <cstdint>
#include <cstddef>

// Problem constants (fixed by setup_inputs)
#define BATCH 2
#define TSEQ  2048
#define EMB   1024
#define NH    16
#define HD    64
#define CHK   128
#define NC    (TSEQ / CHK)          // 16
#define MROWS (BATCH * TSEQ)        // 4096
#define EPS_F 1e-5f

// ---------------- scratch (static device allocations) ----------------
__device__ float g_S [(size_t)BATCH * NH * NC * HD * HD];
__device__ float g_Sp[(size_t)BATCH * NH * NC * HD * HD];
__device__ float g_z [(size_t)BATCH * NH * NC * HD];
__device__ float g_zp[(size_t)BATCH * NH * NC * HD];

// fp16 hi/lo operands
__device__ __half g_xh[(size_t)MROWS * EMB];
__device__ __half g_xl[(size_t)MROWS * EMB];
__device__ __half g_qh[(size_t)MROWS * EMB];
__device__ __half g_ql[(size_t)MROWS * EMB];
__device__ __half g_kh[(size_t)MROWS * EMB];
__device__ __half g_kl[(size_t)MROWS * EMB];
__device__ __half g_vh[(size_t)MROWS * EMB];
__device__ __half g_vl[(size_t)MROWS * EMB];
__device__ __half g_ah[(size_t)MROWS * EMB];
__device__ __half g_al[(size_t)MROWS * EMB];
__device__ __half g_w [(size_t)4 * EMB * EMB]; // Wq, Wk, Wv, Wo (fp16)

// ---------------- PTX helpers (arch-agnostic: valid on target sm_103) ----------------
__device__ __forceinline__ uint32_t smem_u32(const void* p) {
    uint32_t a;
    asm("{ .reg .u64 t; cvta.to.shared.u64 t, %1; cvt.u32.u64 %0, t; }"
        : "=r"(a) : "l"(p));
    return a;
}
__device__ __forceinline__ void cp16(uint32_t s, const void* g) {
    asm volatile("cp.async.cg.shared.global [%0], [%1], 16;" :: "r"(s), "l"(g) : "memory");
}
__device__ __forceinline__ void cp_commit() {
    asm volatile("cp.async.commit_group;" ::: "memory");
}
__device__ __forceinline__ void cp_wait0() {
    asm volatile("cp.async.wait_group 0;" ::: "memory");
}
__device__ __forceinline__ void cp_wait1() {
    asm volatile("cp.async.wait_group 1;" ::: "memory");
}
__device__ __forceinline__ void ldmx4(uint32_t* r, uint32_t addr) {
    asm volatile("ldmatrix.sync.aligned.m8n8.x4.shared.b16 {%0,%1,%2,%3}, [%4];"
                 : "=r"(r[0]), "=r"(r[1]), "=r"(r[2]), "=r"(r[3]) : "r"(addr));
}
__device__ __forceinline__ void ldmx4t(uint32_t* r, uint32_t addr) {
    asm volatile("ldmatrix.sync.aligned.m8n8.x4.trans.shared.b16 {%0,%1,%2,%3}, [%4];"
                 : "=r"(r[0]), "=r"(r[1]), "=r"(r[2]), "=r"(r[3]) : "r"(addr));
}
__device__ __forceinline__ void mma_f16(float* c, const uint32_t* a, const uint32_t* b) {
    asm volatile("mma.sync.aligned.m16n8k16.row.col.f32.f16.f16.f32 "
                 "{%0,%1,%2,%3},{%4,%5,%6,%7},{%8,%9},{%0,%1,%2,%3};"
                 : "+f"(c[0]), "+f"(c[1]), "+f"(c[2]), "+f"(c[3])
                 : "r"(a[0]), "r"(a[1]), "r"(a[2]), "r"(a[3]), "r"(b[0]), "r"(b[1]));
}
__device__ __forceinline__ float phi_f(float v) {
    return (v > 0.f) ? (v + 1.f) : expf(v);
}

// ---------------- hi/lo fp16 split (x only) ----------------
__global__ __launch_bounds__(256)
void split_half_kernel(const float* __restrict__ in,
                       __half* __restrict__ hi, __half* __restrict__ lo, int n4)
{
    int i = blockIdx.x * 256 + threadIdx.x;
    if (i >= n4) return;
    float4 v = reinterpret_cast<const float4*>(in)[i];
    __half2 h01 = __floats2half2_rn(v.x, v.y);
    __half2 h23 = __floats2half2_rn(v.z, v.w);
    float2 f01 = __half22float2(h01);
    float2 f23 = __half22float2(h23);
    reinterpret_cast<__half2*>(hi)[2 * i + 0] = h01;
    reinterpret_cast<__half2*>(hi)[2 * i + 1] = h23;
    reinterpret_cast<__half2*>(lo)[2 * i + 0] = __floats2half2_rn(v.x - f01.x, v.y - f01.y);
    reinterpret_cast<__half2*>(lo)[2 * i + 1] = __floats2half2_rn(v.z - f23.x, v.w - f23.y);
}

// ---------------- fp16 convert for all 4 weights (one launch) ----------------
__global__ __launch_bounds__(256)
void conv_w_kernel(const float* __restrict__ Wq, const float* __restrict__ Wk,
                   const float* __restrict__ Wv, const float* __restrict__ Wo,
                   __half* __restrict__ dst)
{
    const int wsel = blockIdx.y;
    const float* src = (wsel == 0) ? Wq : (wsel == 1) ? Wk : (wsel == 2) ? Wv : Wo;
    int i = blockIdx.x * 256 + threadIdx.x;
    float4 v = reinterpret_cast<const float4*>(src)[i];
    __half2* o = reinterpret_cast<__half2*>(dst + (size_t)wsel * EMB * EMB);
    o[2 * i + 0] = __floats2half2_rn(v.x, v.y);
    o[2 * i + 1] = __floats2half2_rn(v.z, v.w);
}

// ---------------- HMMA 2-pass tile (128x128), C = act( A @ B^T ) ----------------
#define KC        64
#define NKC       (EMB / KC)            // 16
#define ROW_HALF  72
#define ROW_B     (ROW_HALF * 2)        // 144
#define TILE_BY   (128 * ROW_B)         // 18432
#define STAGE_BY  (3 * TILE_BY)         // 55296
#define GEMM_SMEM (2 * STAGE_BY)        // 110592

// OUTF==0: fp16 hi/lo out (optional phi). OUTF==1: fp32 out (+bias).
template <int OUTF>
__device__ __forceinline__ void hmma_tile(
    char* smem, const __half* __restrict__ Ah, const __half* __restrict__ Al,
    const __half* __restrict__ B, int bm, int bn, int do_phi,
    __half* oh, __half* ol, const float* bias, float* Cf)
{
    const uint32_t sb = smem_u32(smem);
    const int tid = threadIdx.x;
    const int wid = tid >> 5;
    const int lid = tid & 31;

    const int m_off = (wid & 3) * 32;
    const int n_off = (wid >> 2) * 64;

    const int q   = lid >> 3;
    const int a_r = ((q & 1) << 3) + (lid & 7);
    const int a_c = (q >> 1) << 3;
    const int b_r = ((q >> 1) << 3) + (lid & 7);
    const int b_c = (q & 1) << 3;

    auto load_chunk = [&](int kc, int stg) {
#pragma unroll
        for (int it = 0; it < 12; it++) {
            int idx = tid + it * 256;
            int t = idx >> 10;
            int r = (idx >> 3) & 127;
            int c = idx & 7;
            uint32_t saddr = sb + stg * STAGE_BY + t * TILE_BY + r * ROW_B + c * 16;
            const __half* src = (t == 0) ? Ah : (t == 1) ? Al : B;
            int grow = (t < 2) ? (bm + r) : (bn + r);
            cp16(saddr, src + (size_t)grow * EMB + kc * KC + c * 8);
        }
        cp_commit();
    };

    float acc[2][8][4];
#pragma unroll
    for (int mt = 0; mt < 2; mt++)
#pragma unroll
        for (int nt = 0; nt < 8; nt++)
#pragma unroll
            for (int e = 0; e < 4; e++) acc[mt][nt][e] = 0.f;

    load_chunk(0, 0);

    for (int kc = 0; kc < NKC; kc++) {
        if (kc + 1 < NKC) { load_chunk(kc + 1, (kc + 1) & 1); cp_wait1(); }
        else              { cp_wait0(); }
        __syncthreads();

        const uint32_t uAh = sb + (kc & 1) * STAGE_BY;
        const uint32_t uAl = uAh + TILE_BY;
        const uint32_t uB  = uAl + TILE_BY;

#pragma unroll
        for (int ks = 0; ks < 4; ks++) {
            const int kcol2 = ks * 32;

            uint32_t bf[4][4];
#pragma unroll
            for (int p = 0; p < 4; p++)
                ldmx4(bf[p], uB + (n_off + p * 16 + b_r) * ROW_B + kcol2 + b_c * 2);

            uint32_t af[2][4];
#pragma unroll
            for (int mt = 0; mt < 2; mt++)
                ldmx4(af[mt], uAh + (m_off + mt * 16 + a_r) * ROW_B + kcol2 + a_c * 2);
#pragma unroll
            for (int mt = 0; mt < 2; mt++)
#pragma unroll
                for (int nt = 0; nt < 8; nt++)
                    mma_f16(acc[mt][nt], af[mt], &bf[nt >> 1][(nt & 1) * 2]);

#pragma unroll
            for (int mt = 0; mt < 2; mt++)
                ldmx4(af[mt], uAl + (m_off + mt * 16 + a_r) * ROW_B + kcol2 + a_c * 2);
#pragma unroll
            for (int mt = 0; mt < 2; mt++)
#pragma unroll
                for (int nt = 0; nt < 8; nt++)
                    mma_f16(acc[mt][nt], af[mt], &bf[nt >> 1][(nt & 1) * 2]);
        }
        __syncthreads();
    }

    const int gr  = lid >> 2;
    const int gc2 = (lid & 3) * 2;
#pragma unroll
    for (int mt = 0; mt < 2; mt++) {
#pragma unroll
        for (int nt = 0; nt < 8; nt++) {
            int row0 = bm + m_off + mt * 16 + gr;
            int col  = bn + n_off + nt * 8 + gc2;
            float v0 = acc[mt][nt][0], v1 = acc[mt][nt][1];
            float v2 = acc[mt][nt][2], v3 = acc[mt][nt][3];
            if (OUTF == 0) {
                if (do_phi) {
                    v0 = phi_f(v0); v1 = phi_f(v1); v2 = phi_f(v2); v3 = phi_f(v3);
                }
                __half h0 = __float2half(v0), h1 = __float2half(v1);
                __half h2 = __float2half(v2), h3 = __float2half(v3);
                *(__half2*)(oh + (size_t)row0 * EMB + col)       = __halves2half2(h0, h1);
                *(__half2*)(oh + (size_t)(row0 + 8) * EMB + col) = __halves2half2(h2, h3);
                *(__half2*)(ol + (size_t)row0 * EMB + col) =
                    __halves2half2(__float2half(v0 - __half2float(h0)),
                                   __float2half(v1 - __half2float(h1)));
                *(__half2*)(ol + (size_t)(row0 + 8) * EMB + col) =
                    __halves2half2(__float2half(v2 - __half2float(h2)),
                                   __float2half(v3 - __half2float(h3)));
            } else {
                float2 bv = *reinterpret_cast<const float2*>(bias + col);
                *reinterpret_cast<float2*>(Cf + (size_t)row0 * EMB + col) =
                    make_float2(v0 + bv.x, v1 + bv.y);
                *reinterpret_cast<float2*>(Cf + (size_t)(row0 + 8) * EMB + col) =
                    make_float2(v2 + bv.x, v3 + bv.y);
            }
        }
    }
}

// ---------------- FFMA fp32 tile (128x128), C = act( A @ B^T ) ----------------
// AHALF==1: A reconstructed from fp16 hi/lo. OUTF as above. Exact fp32 math.
template <int AHALF, int OUTF>
__device__ __forceinline__ void ffma_tile(
    char* smem, const float* __restrict__ Af,
    const __half* __restrict__ Ahh, const __half* __restrict__ All,
    const float* __restrict__ Bf, int bm, int bn, int do_phi,
    __half* oh, __half* ol, const float* bias, float* Cf)
{
    float (*As)[128] = reinterpret_cast<float(*)[128]>(smem);
    float (*Bs)[128] = reinterpret_cast<float(*)[128]>(smem + 16 * 128 * 4);

    const int tid = threadIdx.x;
    const int tx = tid & 15;
    const int ty = tid >> 4;

    float acc[8][8];
#pragma unroll
    for (int i = 0; i < 8; i++)
#pragma unroll
        for (int j = 0; j < 8; j++) acc[i][j] = 0.f;

    for (int k0 = 0; k0 < EMB; k0 += 16) {
#pragma unroll
        for (int it = 0; it < 2; it++) {
            int idx = tid + it * 256;
            int r   = idx >> 2;
            int cq  = (idx & 3) * 4;
            if (AHALF) {
                uint2 ha = *(const uint2*)(Ahh + (size_t)(bm + r) * EMB + k0 + cq);
                uint2 la = *(const uint2*)(All + (size_t)(bm + r) * EMB + k0 + cq);
                float2 f0 = __half22float2(*reinterpret_cast<__half2*>(&ha.x));
                float2 f1 = __half22float2(*reinterpret_cast<__half2*>(&ha.y));
                float2 g0 = __half22float2(*reinterpret_cast<__half2*>(&la.x));
                float2 g1 = __half22float2(*reinterpret_cast<__half2*>(&la.y));
                As[cq + 0][r] = f0.x + g0.x; As[cq + 1][r] = f0.y + g0.y;
                As[cq + 2][r] = f1.x + g1.x; As[cq + 3][r] = f1.y + g1.y;
            } else {
                float4 va = *(const float4*)(Af + (size_t)(bm + r) * EMB + k0 + cq);
                As[cq + 0][r] = va.x; As[cq + 1][r] = va.y;
                As[cq + 2][r] = va.z; As[cq + 3][r] = va.w;
            }
            float4 vb = *(const float4*)(Bf + (size_t)(bn + r) * EMB + k0 + cq);
            Bs[cq + 0][r] = vb.x; Bs[cq + 1][r] = vb.y;
            Bs[cq + 2][r] = vb.z; Bs[cq + 3][r] = vb.w;
        }
        __syncthreads();

#pragma unroll
        for (int kk = 0; kk < 16; kk++) {
            float ra[8], rb[8];
#pragma unroll
            for (int i = 0; i < 8; i++) ra[i] = As[kk][ty * 8 + i];
#pragma unroll
            for (int j = 0; j < 8; j++) rb[j] = Bs[kk][tx * 8 + j];
#pragma unroll
            for (int i = 0; i < 8; i++)
#pragma unroll
                for (int j = 0; j < 8; j++)
                    acc[i][j] = fmaf(ra[i], rb[j], acc[i][j]);
        }
        __syncthreads();
    }

#pragma unroll
    for (int i = 0; i < 8; i++) {
        int row = bm + ty * 8 + i;
#pragma unroll
        for (int j = 0; j < 8; j++) {
            int col = bn + tx * 8 + j;
            float v = acc[i][j];
            if (OUTF == 0) {
                if (do_phi) v = phi_f(v);
                __half h = __float2half(v);
                oh[(size_t)row * EMB + col] = h;
                ol[(size_t)row * EMB + col] = __float2half(v - __half2float(h));
            } else {
                Cf[(size_t)row * EMB + col] = v + bias[col];
            }
        }
    }
}

// ---------------- fused QKV: hybrid HMMA + FFMA CTAs ----------------
__global__ __launch_bounds__(256, 2)
void qkv_fused(const __half* __restrict__ xh, const __half* __restrict__ xl,
               const float* __restrict__ xf, const __half* __restrict__ wh16,
               const float* __restrict__ Wq, const float* __restrict__ Wk,
               const float* __restrict__ Wv,
               __half* __restrict__ qh, __half* __restrict__ ql,
               __half* __restrict__ kh, __half* __restrict__ kl,
               __half* __restrict__ vh, __half* __restrict__ vl)
{
    extern __shared__ char smem[];
    const int blk = blockIdx.x;                  // 768 blocks
    const int z   = blk % 3;                     // 0:Q 1:K 2:V
    const int t   = blk / 3;                     // 0..255
    const int bn  = (t & 7) * 128;
    const int bm  = (t >> 3) * 128;
    __half* oh = (z == 0) ? qh : (z == 1) ? kh : vh;
    __half* ol = (z == 0) ? ql : (z == 1) ? kl : vl;
    const int do_phi = (z < 2);

    if ((blk & 31) < 25) {
        hmma_tile<0>(smem, xh, xl, wh16 + (size_t)z * EMB * EMB, bm, bn, do_phi,
                     oh, ol, nullptr, nullptr);
    } else {
        const float* wf = (z == 0) ? Wq : (z == 1) ? Wk : Wv;
        ffma_tile<0, 0>(smem, xf, nullptr, nullptr, wf, bm, bn, do_phi,
                        oh, ol, nullptr, nullptr);
    }
}

// ---------------- fused O projection: hybrid HMMA + FFMA CTAs ----------------
__global__ __launch_bounds__(256, 2)
void oproj_fused(const __half* __restrict__ ah, const __half* __restrict__ al,
                 const __half* __restrict__ wo16, const float* __restrict__ Wo,
                 const float* __restrict__ bias, float* __restrict__ out)
{
    extern __shared__ char smem[];
    const int blk = blockIdx.x;                  // 256 blocks
    const int m   = blk & 31;
    const int n   = blk >> 5;
    const int bm  = m * 128;
    const int bn  = n * 128;

    if (m < 25) {
        hmma_tile<1>(smem, ah, al, wo16, bm, bn, 0, nullptr, nullptr, bias, out);
    } else {
        ffma_tile<1, 1>(smem, nullptr, ah, al, Wo, bm, bn, 0, nullptr, nullptr, bias, out);
    }
}

// ---------------- Phase A (tensor-core): S_c = k^T v,  z_c = sum_j k ----------------
#define CS_KH 0
#define CS_KL 18432
#define CS_VH 36864
#define CS_VL 55296
#define CS_SMEM 73728

__global__ __launch_bounds__(256)
void chunk_stats_tc(const __half* __restrict__ Kh, const __half* __restrict__ Kl,
                    const __half* __restrict__ Vh, const __half* __restrict__ Vl,
                    float* __restrict__ gS, float* __restrict__ gZ)
{
    extern __shared__ char smem[];
    const uint32_t sb = smem_u32(smem);

    const int blk = blockIdx.x;
    const int c   = blk % NC;
    const int bh  = blk / NC;
    const int b   = bh / NH;
    const int h   = bh % NH;
    const int tid = threadIdx.x;
    const int wid = tid >> 5;
    const int lid = tid & 31;

    const size_t base = ((size_t)(b * TSEQ) + (size_t)c * CHK) * EMB + (size_t)h * HD;

    const __half* srcs[4] = {Kh + base, Kl + base, Vh + base, Vl + base};
    const uint32_t dofs[4] = {CS_KH, CS_KL, CS_VH, CS_VL};
#pragma unroll
    for (int it = 0; it < 16; it++) {
        int idx = tid + it * 256;
        int t = idx >> 10, r = (idx >> 3) & 127, c8 = (idx & 7) * 8;
        uint4 v = *reinterpret_cast<const uint4*>(srcs[t] + (size_t)r * EMB + c8);
        *reinterpret_cast<uint4*>(smem + dofs[t] + r * ROW_B + c8 * 2) = v;
    }
    __syncthreads();

    const int q   = lid >> 3;
    const int a_r = ((q & 1) << 3) + (lid & 7);
    const int a_c = (q >> 1) << 3;
    const int b_r = ((q >> 1) << 3) + (lid & 7);
    const int b_c = (q & 1) << 3;

    const int m_off = (wid & 3) * 16;
    const int n_off = (wid >> 2) * 32;

    float acc[4][4];
#pragma unroll
    for (int nt = 0; nt < 4; nt++)
#pragma unroll
        for (int e = 0; e < 4; e++) acc[nt][e] = 0.f;

#pragma unroll
    for (int ks = 0; ks < 8; ks++) {
        const int jb = ks * 16;
        uint32_t afh[4], afl[4];
        ldmx4t(afh, sb + CS_KH + (jb + b_r) * ROW_B + (m_off + b_c) * 2);
        uint32_t bfh[2][4];
#pragma unroll
        for (int p = 0; p < 2; p++)
            ldmx4t(bfh[p], sb + CS_VH + (jb + a_r) * ROW_B + (n_off + p * 16 + a_c) * 2);
#pragma unroll
        for (int nt = 0; nt < 4; nt++)
            mma_f16(acc[nt], afh, &bfh[nt >> 1][(nt & 1) * 2]);

        uint32_t bfl[2][4];
#pragma unroll
        for (int p = 0; p < 2; p++)
            ldmx4t(bfl[p], sb + CS_VL + (jb + a_r) * ROW_B + (n_off + p * 16 + a_c) * 2);
#pragma unroll
        for (int nt = 0; nt < 4; nt++)
            mma_f16(acc[nt], afh, &bfl[nt >> 1][(nt & 1) * 2]);

        ldmx4t(afl, sb + CS_KL + (jb + b_r) * ROW_B + (m_off + b_c) * 2);
#pragma unroll
        for (int nt = 0; nt < 4; nt++)
            mma_f16(acc[nt], afl, &bfh[nt >> 1][(nt & 1) * 2]);
    }

    const int gr  = lid >> 2;
    const int gc2 = (lid & 3) * 2;
    float* Sout = gS + (size_t)blk * (HD * HD);
#pragma unroll
    for (int nt = 0; nt < 4; nt++) {
        int row0 = m_off + gr;
        int col  = n_off + nt * 8 + gc2;
        *reinterpret_cast<float2*>(Sout + (size_t)row0 * HD + col) =
            make_float2(acc[nt][0], acc[nt][1]);
        *reinterpret_cast<float2*>(Sout + (size_t)(row0 + 8) * HD + col) =
            make_float2(acc[nt][2], acc[nt][3]);
    }

    if (tid < HD) {
        const __half* kh = reinterpret_cast<const __half*>(smem + CS_KH);
        const __half* kl = reinterpret_cast<const __half*>(smem + CS_KL);
        float zsum = 0.f;
        for (int j = 0; j < CHK; j++)
            zsum += __half2float(kh[j * ROW_HALF + tid]) + __half2float(kl[j * ROW_HALF + tid]);
        gZ[(size_t)blk * HD + tid] = zsum;
    }
}

// ---------------- Phase B: exclusive prefix over chunks ----------------
__global__ __launch_bounds__(256)
void prefix_kernel(const float* __restrict__ gS, const float* __restrict__ gZ,
                   float* __restrict__ gSp, float* __restrict__ gZp)
{
    const int bh  = blockIdx.x;
    const int tid = threadIdx.x;

    float acc[16];
#pragma unroll
    for (int i = 0; i < 16; i++) acc[i] = 0.f;

    for (int c = 0; c < NC; c++) {
        size_t off = ((size_t)bh * NC + c) * (HD * HD);
#pragma unroll
        for (int i = 0; i < 16; i++) {
            gSp[off + tid * 16 + i] = acc[i];
            acc[i] += gS[off + tid * 16 + i];
        }
    }
    if (tid < HD) {
        float z = 0.f;
        for (int c = 0; c < NC; c++) {
            size_t off = ((size_t)bh * NC + c) * HD;
            gZp[off + tid] = z;
            z += gZ[off + tid];
        }
    }
}

// ---------------- Phase C: tensor-core per-chunk output ----------------
// P1 3-pass; P3 2-pass (A hi+lo x v_hi; q hi+lo x Sp_hi). No v_lo / Sp_lo in smem.
#define QROWB  144
#define AROWB  272
#define OFF_QH   0
#define OFF_QL   18432
#define OFF_KH   36864
#define OFF_KL   55296
#define OFF_AH   73728
#define OFF_AL   108544
#define OFF_VH   143360
#define OFF_SPH  161792
#define OFF_ZC   171008
#define OFF_DEN  171264
#define OFF_RSP  171776
#define ATTN_SMEM 172800

__global__ __launch_bounds__(256, 1)
void attn_mma_kernel(const __half* __restrict__ Qh_g, const __half* __restrict__ Ql_g,
                     const __half* __restrict__ Kh_g, const __half* __restrict__ Kl_g,
                     const __half* __restrict__ Vh_g,
                     const float* __restrict__ gSp, const float* __restrict__ gZp,
                     __half* __restrict__ Oh, __half* __restrict__ Ol)
{
    extern __shared__ char smem[];
    const uint32_t sb = smem_u32(smem);

    const int blk = blockIdx.x;
    const int c   = blk % NC;
    const int bh  = blk / NC;
    const int b   = bh / NH;
    const int h   = bh % NH;
    const int tid = threadIdx.x;
    const int wid = tid >> 5;
    const int lid = tid & 31;

    const size_t base = ((size_t)(b * TSEQ) + (size_t)c * CHK) * EMB + (size_t)h * HD;

    float* zcs  = reinterpret_cast<float*>(smem + OFF_ZC);
    float* den  = reinterpret_cast<float*>(smem + OFF_DEN);
    float* rsP  = reinterpret_cast<float*>(smem + OFF_RSP);   // [128][2]

    // ---- P0: coalesced fp16 copies (Q,K hi/lo + V hi) + Sp hi split ----
    {
        const __half* srcs[5] = {Qh_g + base, Ql_g + base, Kh_g + base,
                                 Kl_g + base, Vh_g + base};
        const uint32_t dofs[5] = {OFF_QH, OFF_QL, OFF_KH, OFF_KL, OFF_VH};
#pragma unroll
        for (int it = 0; it < 20; it++) {
            int idx = tid + it * 256;
            int t = idx >> 10, r = (idx >> 3) & 127, c8 = (idx & 7) * 8;
            uint4 v = *reinterpret_cast<const uint4*>(srcs[t] + (size_t)r * EMB + c8);
            *reinterpret_cast<uint4*>(smem + dofs[t] + r * QROWB + c8 * 2) = v;
        }
    }
#pragma unroll
    for (int it = 0; it < 4; it++) {
        int idx = tid + it * 256;                 // 1024 float4 slots
        int d = idx >> 4, e4 = (idx & 15) * 4;
        float4 v = *(const float4*)(gSp + (size_t)blk * (HD * HD) + (size_t)d * HD + e4);
        char* ph = smem + OFF_SPH + d * QROWB + e4 * 2;
        *(__half2*)(ph)     = __floats2half2_rn(v.x, v.y);
        *(__half2*)(ph + 4) = __floats2half2_rn(v.z, v.w);
    }
    if (tid < HD) zcs[tid] = gZp[(size_t)blk * HD + tid];
    __syncthreads();

    const int q   = lid >> 3;
    const int a_r = ((q & 1) << 3) + (lid & 7);
    const int a_c = (q >> 1) << 3;
    const int b_r = ((q >> 1) << 3) + (lid & 7);
    const int b_c = (q & 1) << 3;
    const int gr  = lid >> 2;
    const int gc2 = (lid & 3) * 2;

    // ---- P1: A = q k^T, 3-pass, warp tile 32x64 ----
    {
        const int m_off = (wid & 3) * 32;
        const int n_off = (wid >> 2) * 64;
        const int wn    = wid >> 2;

        float acc[2][8][4];
#pragma unroll
        for (int mt = 0; mt < 2; mt++)
#pragma unroll
            for (int nt = 0; nt < 8; nt++)
#pragma unroll
                for (int e = 0; e < 4; e++) acc[mt][nt][e] = 0.f;

#pragma unroll
        for (int ks = 0; ks < 4; ks++) {
            const int kcol = ks * 32;
            uint32_t bfh[4][4];
#pragma unroll
            for (int p = 0; p < 4; p++)
                ldmx4(bfh[p], sb + OFF_KH + (n_off + p * 16 + b_r) * QROWB + kcol + b_c * 2);
            uint32_t af[2][4];
#pragma unroll
            for (int mt = 0; mt < 2; mt++)
                ldmx4(af[mt], sb + OFF_QH + (m_off + mt * 16 + a_r) * QROWB + kcol + a_c * 2);
#pragma unroll
            for (int mt = 0; mt < 2; mt++)
#pragma unroll
                for (int nt = 0; nt < 8; nt++)
                    mma_f16(acc[mt][nt], af[mt], &bfh[nt >> 1][(nt & 1) * 2]);
            uint32_t bfl[4][4];
#pragma unroll
            for (int p = 0; p < 4; p++)
                ldmx4(bfl[p], sb + OFF_KL + (n_off + p * 16 + b_r) * QROWB + kcol + b_c * 2);
#pragma unroll
            for (int mt = 0; mt < 2; mt++)
#pragma unroll
                for (int nt = 0; nt < 8; nt++)
                    mma_f16(acc[mt][nt], af[mt], &bfl[nt >> 1][(nt & 1) * 2]);
#pragma unroll
            for (int mt = 0; mt < 2; mt++)
                ldmx4(af[mt], sb + OFF_QL + (m_off + mt * 16 + a_r) * QROWB + kcol + a_c * 2);
#pragma unroll
            for (int mt = 0; mt < 2; mt++)
#pragma unroll
                for (int nt = 0; nt < 8; nt++)
                    mma_f16(acc[mt][nt], af[mt], &bfh[nt >> 1][(nt & 1) * 2]);
        }

        // mask + rowsum + hi/lo store of A
#pragma unroll
        for (int mt = 0; mt < 2; mt++) {
            const int r0 = m_off + mt * 16 + gr;
            const int r1 = r0 + 8;
            float s0 = 0.f, s1 = 0.f;
#pragma unroll
            for (int nt = 0; nt < 8; nt++) {
                const int col = n_off + nt * 8 + gc2;
                float c0 = (col     <= r0) ? acc[mt][nt][0] : 0.f;
                float c1 = (col + 1 <= r0) ? acc[mt][nt][1] : 0.f;
                float c2 = (col     <= r1) ? acc[mt][nt][2] : 0.f;
                float c3 = (col + 1 <= r1) ? acc[mt][nt][3] : 0.f;
                s0 += c0 + c1;
                s1 += c2 + c3;
                __half h0 = __float2half(c0), h1 = __float2half(c1);
                __half h2 = __float2half(c2), h3 = __float2half(c3);
                *(__half2*)(smem + OFF_AH + r0 * AROWB + col * 2) = __halves2half2(h0, h1);
                *(__half2*)(smem + OFF_AH + r1 * AROWB + col * 2) = __halves2half2(h2, h3);
                *(__half2*)(smem + OFF_AL + r0 * AROWB + col * 2) =
                    __halves2half2(__float2half(c0 - __half2float(h0)),
                                   __float2half(c1 - __half2float(h1)));
                *(__half2*)(smem + OFF_AL + r1 * AROWB + col * 2) =
                    __halves2half2(__float2half(c2 - __half2float(h2)),
                                   __float2half(c3 - __half2float(h3)));
            }
            s0 += __shfl_xor_sync(0xffffffffu, s0, 1);
            s0 += __shfl_xor_sync(0xffffffffu, s0, 2);
            s1 += __shfl_xor_sync(0xffffffffu, s1, 1);
            s1 += __shfl_xor_sync(0xffffffffu, s1, 2);
            if ((lid & 3) == 0) {
                rsP[r0 * 2 + wn] = s0;
                rsP[r1 * 2 + wn] = s1;
            }
        }
    }
    __syncthreads();

    // ---- P2: den ----
    if (tid < CHK) {
        float rs = rsP[tid * 2 + 0] + rsP[tid * 2 + 1];
        float qz = 0.f;
#pragma unroll
        for (int d = 0; d < HD; d++) {
            float qv = __half2float(*(const __half*)(smem + OFF_QH + tid * QROWB + d * 2))
                     + __half2float(*(const __half*)(smem + OFF_QL + tid * QROWB + d * 2));
            qz += qv * zcs[d];
        }
        den[tid] = rs + qz + EPS_F;
    }

    // ---- P3: num = A@v + q@Sp, 2-pass each, warp tile 32x32 ----
    const int m_off3 = (wid & 3) * 32;
    const int n_off3 = (wid >> 2) * 32;
    float o[2][4][4];
#pragma unroll
    for (int mt = 0; mt < 2; mt++)
#pragma unroll
        for (int nt = 0; nt < 4; nt++)
#pragma unroll
            for (int e = 0; e < 4; e++) o[mt][nt][e] = 0.f;

    // (a) (A_h + A_l) @ v_h : K-dim = 128
#pragma unroll
    for (int ks = 0; ks < 8; ks++) {
        const int jb = ks * 16;
        const int kcol = ks * 32;
        uint32_t bfh[2][4];
#pragma unroll
        for (int p = 0; p < 2; p++)
            ldmx4t(bfh[p], sb + OFF_VH + (jb + a_r) * QROWB + (n_off3 + p * 16 + a_c) * 2);
        uint32_t af[2][4];
#pragma unroll
        for (int mt = 0; mt < 2; mt++)
            ldmx4(af[mt], sb + OFF_AH + (m_off3 + mt * 16 + a_r) * AROWB + kcol + a_c * 2);
#pragma unroll
        for (int mt = 0; mt < 2; mt++)
#pragma unroll
            for (int nt = 0; nt < 4; nt++)
                mma_f16(o[mt][nt], af[mt], &bfh[nt >> 1][(nt & 1) * 2]);
#pragma unroll
        for (int mt = 0; mt < 2; mt++)
            ldmx4(af[mt], sb + OFF_AL + (m_off3 + mt * 16 + a_r) * AROWB + kcol + a_c * 2);
#pragma unroll
        for (int mt = 0; mt < 2; mt++)
#pragma unroll
            for (int nt = 0; nt < 4; nt++)
                mma_f16(o[mt][nt], af[mt], &bfh[nt >> 1][(nt & 1) * 2]);
    }

    // (b) (q_h + q_l) @ Sp_h : K-dim = 64
#pragma unroll
    for (int ks = 0; ks < 4; ks++) {
        const int db = ks * 16;
        const int kcol = ks * 32;
        uint32_t bfh[2][4];
#pragma unroll
        for (int p = 0; p < 2; p++)
            ldmx4t(bfh[p], sb + OFF_SPH + (db + a_r) * QROWB + (n_off3 + p * 16 + a_c) * 2);
        uint32_t af[2][4];
#pragma unroll
        for (int mt = 0; mt < 2; mt++)
            ldmx4(af[mt], sb + OFF_QH + (m_off3 + mt * 16 + a_r) * QROWB + kcol + a_c * 2);
#pragma unroll
        for (int mt = 0; mt < 2; mt++)
#pragma unroll
            for (int nt = 0; nt < 4; nt++)
                mma_f16(o[mt][nt], af[mt], &bfh[nt >> 1][(nt & 1) * 2]);
#pragma unroll
        for (int mt = 0; mt < 2; mt++)
            ldmx4(af[mt], sb + OFF_QL + (m_off3 + mt * 16 + a_r) * QROWB + kcol + a_c * 2);
#pragma unroll
        for (int mt = 0; mt < 2; mt++)
#pragma unroll
            for (int nt = 0; nt < 4; nt++)
                mma_f16(o[mt][nt], af[mt], &bfh[nt >> 1][(nt & 1) * 2]);
    }
    __syncthreads();   // den ready; QH/QL reads done

    // ---- P4: divide by den, stage hi/lo into (reused) QH/QL regions ----
#pragma unroll
    for (int mt = 0; mt < 2; mt++) {
        const int r0 = m_off3 + mt * 16 + gr;
        const int r1 = r0 + 8;
        const float i0 = 1.f / den[r0];
        const float i1 = 1.f / den[r1];
#pragma unroll
        for (int nt = 0; nt < 4; nt++) {
            const int col = n_off3 + nt * 8 + gc2;
            float y0 = o[mt][nt][0] * i0;
            float y1 = o[mt][nt][1] * i0;
            float y2 = o[mt][nt][2] * i1;
            float y3 = o[mt][nt][3] * i1;
            __half h0 = __float2half(y0), h1 = __float2half(y1);
            __half h2 = __float2half(y2), h3 = __float2half(y3);
            *(__half2*)(smem + OFF_QH + r0 * QROWB + col * 2) = __halves2half2(h0, h1);
            *(__half2*)(smem + OFF_QH + r1 * QROWB + col * 2) = __halves2half2(h2, h3);
            *(__half2*)(smem + OFF_QL + r0 * QROWB + col * 2) =
                __halves2half2(__float2half(y0 - __half2float(h0)),
                               __float2half(y1 - __half2float(h1)));
            *(__half2*)(smem + OFF_QL + r1 * QROWB + col * 2) =
                __halves2half2(__float2half(y2 - __half2float(h2)),
                               __float2half(y3 - __half2float(h3)));
        }
    }
    __syncthreads();

    // ---- P5: coalesced global writes of hi/lo output ----
#pragma unroll
    for (int it = 0; it < 8; it++) {
        int idx = tid + it * 256;
        int r = idx >> 4, c4 = (idx & 15) * 4;
        uint2 vh = *(const uint2*)(smem + OFF_QH + r * QROWB + c4 * 2);
        uint2 vl = *(const uint2*)(smem + OFF_QL + r * QROWB + c4 * 2);
        *reinterpret_cast<uint2*>(Oh + base + (size_t)r * EMB + c4) = vh;
        *reinterpret_cast<uint2*>(Ol + base + (size_t)r * EMB + c4) = vl;
    }
}

// ---------------- launch ----------------
extern "C" void kernel_launch(void* const* d_in, const int* in_sizes, int n_in,
                              void* d_out, int out_size)
{
    const float* x  = (const float*)d_in[0];
    const float* Wq = (const float*)d_in[1];
    const float* Wk = (const float*)d_in[2];
    const float* Wv = (const float*)d_in[3];
    const float* Wo = (const float*)d_in[4];
    const float* bo = (const float*)d_in[5];
    float* out = (float*)d_out;
    (void)in_sizes; (void)n_in; (void)out_size;

    float *pS, *pSp, *pZ, *pZp;
    cudaGetSymbolAddress((void**)&pS,  g_S);
    cudaGetSymbolAddress((void**)&pSp, g_Sp);
    cudaGetSymbolAddress((void**)&pZ,  g_z);
    cudaGetSymbolAddress((void**)&pZp, g_zp);

    __half *xh, *xl, *qh_, *ql_, *kh_, *kl_, *vh_, *vl_, *ah, *al, *wh;
    cudaGetSymbolAddress((void**)&xh,  g_xh);
    cudaGetSymbolAddress((void**)&xl,  g_xl);
    cudaGetSymbolAddress((void**)&qh_, g_qh);
    cudaGetSymbolAddress((void**)&ql_, g_ql);
    cudaGetSymbolAddress((void**)&kh_, g_kh);
    cudaGetSymbolAddress((void**)&kl_, g_kl);
    cudaGetSymbolAddress((void**)&vh_, g_vh);
    cudaGetSymbolAddress((void**)&vl_, g_vl);
    cudaGetSymbolAddress((void**)&ah,  g_ah);
    cudaGetSymbolAddress((void**)&al,  g_al);
    cudaGetSymbolAddress((void**)&wh,  g_w);

    cudaFuncSetAttribute(qkv_fused,
                         cudaFuncAttributeMaxDynamicSharedMemorySize, GEMM_SMEM);
    cudaFuncSetAttribute(oproj_fused,
                         cudaFuncAttributeMaxDynamicSharedMemorySize, GEMM_SMEM);
    cudaFuncSetAttribute(chunk_stats_tc,
                         cudaFuncAttributeMaxDynamicSharedMemorySize, CS_SMEM);
    cudaFuncSetAttribute(attn_mma_kernel,
                         cudaFuncAttributeMaxDynamicSharedMemorySize, ATTN_SMEM);

    const int n4x = MROWS * EMB / 4;   // 1048576
    const int n4w = EMB * EMB / 4;     // 262144

    // operand conversion
    split_half_kernel<<<n4x / 256, 256>>>(x, xh, xl, n4x);
    conv_w_kernel<<<dim3(n4w / 256, 4), 256>>>(Wq, Wk, Wv, Wo, wh);

    // Hybrid fused Q/K/V projections (HMMA tiles + FFMA tiles, phi fused)
    qkv_fused<<<768, 256, GEMM_SMEM>>>(xh, xl, x, wh, Wq, Wk, Wv,
                                       qh_, ql_, kh_, kl_, vh_, vl_);

    // Chunked recurrent state: tc stats -> prefix -> tc output (emits fp16 hi/lo)
    chunk_stats_tc<<<BATCH * NH * NC, 256, CS_SMEM>>>(kh_, kl_, vh_, vl_, pS, pZ);
    prefix_kernel<<<BATCH * NH, 256>>>(pS, pZ, pSp, pZp);
    attn_mma_kernel<<<BATCH * NH * NC, 256, ATTN_SMEM>>>(qh_, ql_, kh_, kl_, vh_,
                                                         pSp, pZp, ah, al);

    // Hybrid output projection + bias (fp32 out)
    oproj_fused<<<256, 256, GEMM_SMEM>>>(ah, al, wh + (size_t)3 * EMB * EMB, Wo, bo, out);
}

// round 15
// speedup vs baseline: 2.3897x; 2.3897x over previous
#include <cuda_runtime.h>
#include <cuda_fp16.h>
#include <cstdint>
#include <cstddef>

// Problem constants (fixed by setup_inputs)
#define BATCH 2
#define TSEQ  2048
#define EMB   1024
#define NH    16
#define HD    64
#define CHK   128
#define NC    (TSEQ / CHK)          // 16
#define MROWS (BATCH * TSEQ)        // 4096
#define EPS_F 1e-5f

// ---------------- scratch (static device allocations) ----------------
__device__ float g_S [(size_t)BATCH * NH * NC * HD * HD];
__device__ float g_Sp[(size_t)BATCH * NH * NC * HD * HD];
__device__ float g_z [(size_t)BATCH * NH * NC * HD];
__device__ float g_zp[(size_t)BATCH * NH * NC * HD];

// fp16 hi/lo operands
__device__ __half g_xh[(size_t)MROWS * EMB];
__device__ __half g_xl[(size_t)MROWS * EMB];
__device__ __half g_qh[(size_t)MROWS * EMB];
__device__ __half g_ql[(size_t)MROWS * EMB];
__device__ __half g_kh[(size_t)MROWS * EMB];
__device__ __half g_kl[(size_t)MROWS * EMB];
__device__ __half g_vh[(size_t)MROWS * EMB];
__device__ __half g_vl[(size_t)MROWS * EMB];
__device__ __half g_ah[(size_t)MROWS * EMB];
__device__ __half g_al[(size_t)MROWS * EMB];
__device__ __half g_w [(size_t)4 * EMB * EMB]; // Wq, Wk, Wv, Wo (fp16)

// ---------------- PTX helpers (arch-agnostic: valid on target sm_103) ----------------
__device__ __forceinline__ uint32_t smem_u32(const void* p) {
    uint32_t a;
    asm("{ .reg .u64 t; cvta.to.shared.u64 t, %1; cvt.u32.u64 %0, t; }"
        : "=r"(a) : "l"(p));
    return a;
}
__device__ __forceinline__ void cp16(uint32_t s, const void* g) {
    asm volatile("cp.async.cg.shared.global [%0], [%1], 16;" :: "r"(s), "l"(g) : "memory");
}
__device__ __forceinline__ void cp_commit() {
    asm volatile("cp.async.commit_group;" ::: "memory");
}
__device__ __forceinline__ void cp_wait0() {
    asm volatile("cp.async.wait_group 0;" ::: "memory");
}
__device__ __forceinline__ void cp_wait1() {
    asm volatile("cp.async.wait_group 1;" ::: "memory");
}
__device__ __forceinline__ void ldmx4(uint32_t* r, uint32_t addr) {
    asm volatile("ldmatrix.sync.aligned.m8n8.x4.shared.b16 {%0,%1,%2,%3}, [%4];"
                 : "=r"(r[0]), "=r"(r[1]), "=r"(r[2]), "=r"(r[3]) : "r"(addr));
}
__device__ __forceinline__ void ldmx4t(uint32_t* r, uint32_t addr) {
    asm volatile("ldmatrix.sync.aligned.m8n8.x4.trans.shared.b16 {%0,%1,%2,%3}, [%4];"
                 : "=r"(r[0]), "=r"(r[1]), "=r"(r[2]), "=r"(r[3]) : "r"(addr));
}
__device__ __forceinline__ void mma_f16(float* c, const uint32_t* a, const uint32_t* b) {
    asm volatile("mma.sync.aligned.m16n8k16.row.col.f32.f16.f16.f32 "
                 "{%0,%1,%2,%3},{%4,%5,%6,%7},{%8,%9},{%0,%1,%2,%3};"
                 : "+f"(c[0]), "+f"(c[1]), "+f"(c[2]), "+f"(c[3])
                 : "r"(a[0]), "r"(a[1]), "r"(a[2]), "r"(a[3]), "r"(b[0]), "r"(b[1]));
}

// ---------------- hi/lo fp16 split (x only) ----------------
__global__ __launch_bounds__(256)
void split_half_kernel(const float* __restrict__ in,
                       __half* __restrict__ hi, __half* __restrict__ lo, int n4)
{
    int i = blockIdx.x * 256 + threadIdx.x;
    if (i >= n4) return;
    float4 v = reinterpret_cast<const float4*>(in)[i];
    __half2 h01 = __floats2half2_rn(v.x, v.y);
    __half2 h23 = __floats2half2_rn(v.z, v.w);
    float2 f01 = __half22float2(h01);
    float2 f23 = __half22float2(h23);
    reinterpret_cast<__half2*>(hi)[2 * i + 0] = h01;
    reinterpret_cast<__half2*>(hi)[2 * i + 1] = h23;
    reinterpret_cast<__half2*>(lo)[2 * i + 0] = __floats2half2_rn(v.x - f01.x, v.y - f01.y);
    reinterpret_cast<__half2*>(lo)[2 * i + 1] = __floats2half2_rn(v.z - f23.x, v.w - f23.y);
}

// ---------------- fp16 convert for all 4 weights (one launch) ----------------
__global__ __launch_bounds__(256)
void conv_w_kernel(const float* __restrict__ Wq, const float* __restrict__ Wk,
                   const float* __restrict__ Wv, const float* __restrict__ Wo,
                   __half* __restrict__ dst)
{
    const int wsel = blockIdx.y;
    const float* src = (wsel == 0) ? Wq : (wsel == 1) ? Wk : (wsel == 2) ? Wv : Wo;
    int i = blockIdx.x * 256 + threadIdx.x;
    float4 v = reinterpret_cast<const float4*>(src)[i];
    __half2* o = reinterpret_cast<__half2*>(dst + (size_t)wsel * EMB * EMB);
    o[2 * i + 0] = __floats2half2_rn(v.x, v.y);
    o[2 * i + 1] = __floats2half2_rn(v.z, v.w);
}

// ---------------- mma.sync fp16 2-pass GEMM: C = act( A @ W^T ) ----------------
// MODE 0: fused QKV, emits fp16 hi/lo outputs (phi for z<2)
// MODE 1: output projection (+bias), emits fp32
#define KC        64
#define NKC       (EMB / KC)            // 16
#define ROW_HALF  72
#define ROW_B     (ROW_HALF * 2)        // 144
#define TILE_BY   (128 * ROW_B)         // 18432
#define STAGE_BY  (3 * TILE_BY)         // 55296
#define GEMM_SMEM (2 * STAGE_BY)        // 110592

template <int MODE>
__global__ __launch_bounds__(256, 2)
void mma_gemm_half(const __half* __restrict__ Ah, const __half* __restrict__ Al,
                   const __half* __restrict__ Wall, const float* __restrict__ bias,
                   float* __restrict__ Cf,
                   __half* __restrict__ OhQ, __half* __restrict__ OlQ,
                   __half* __restrict__ OhK, __half* __restrict__ OlK,
                   __half* __restrict__ OhV, __half* __restrict__ OlV)
{
    extern __shared__ char smem[];
    const uint32_t sb = smem_u32(smem);

    const int z = (MODE == 0) ? blockIdx.z : 0;
    const __half* B = Wall + (size_t)z * EMB * EMB;
    __half* oh = (z == 0) ? OhQ : (z == 1) ? OhK : OhV;
    __half* ol = (z == 0) ? OlQ : (z == 1) ? OlK : OlV;
    const int do_phi = (MODE == 0) && (z < 2);

    const int tid = threadIdx.x;
    const int wid = tid >> 5;
    const int lid = tid & 31;
    const int bm  = blockIdx.y * 128;
    const int bn  = blockIdx.x * 128;

    const int m_off = (wid & 3) * 32;
    const int n_off = (wid >> 2) * 64;

    const int q   = lid >> 3;
    const int a_r = ((q & 1) << 3) + (lid & 7);
    const int a_c = (q >> 1) << 3;
    const int b_r = ((q >> 1) << 3) + (lid & 7);
    const int b_c = (q & 1) << 3;

    auto load_chunk = [&](int kc, int stg) {
#pragma unroll
        for (int it = 0; it < 12; it++) {
            int idx = tid + it * 256;
            int t = idx >> 10;
            int r = (idx >> 3) & 127;
            int c = idx & 7;
            uint32_t saddr = sb + stg * STAGE_BY + t * TILE_BY + r * ROW_B + c * 16;
            const __half* src = (t == 0) ? Ah : (t == 1) ? Al : B;
            int grow = (t < 2) ? (bm + r) : (bn + r);
            cp16(saddr, src + (size_t)grow * EMB + kc * KC + c * 8);
        }
        cp_commit();
    };

    float acc[2][8][4];
#pragma unroll
    for (int mt = 0; mt < 2; mt++)
#pragma unroll
        for (int nt = 0; nt < 8; nt++)
#pragma unroll
            for (int e = 0; e < 4; e++) acc[mt][nt][e] = 0.f;

    load_chunk(0, 0);

    for (int kc = 0; kc < NKC; kc++) {
        if (kc + 1 < NKC) { load_chunk(kc + 1, (kc + 1) & 1); cp_wait1(); }
        else              { cp_wait0(); }
        __syncthreads();

        const uint32_t uAh = sb + (kc & 1) * STAGE_BY;
        const uint32_t uAl = uAh + TILE_BY;
        const uint32_t uB  = uAl + TILE_BY;

#pragma unroll
        for (int ks = 0; ks < 4; ks++) {
            const int kcol2 = ks * 32;

            uint32_t bf[4][4];
#pragma unroll
            for (int p = 0; p < 4; p++)
                ldmx4(bf[p], uB + (n_off + p * 16 + b_r) * ROW_B + kcol2 + b_c * 2);

            uint32_t af[2][4];
#pragma unroll
            for (int mt = 0; mt < 2; mt++)
                ldmx4(af[mt], uAh + (m_off + mt * 16 + a_r) * ROW_B + kcol2 + a_c * 2);
#pragma unroll
            for (int mt = 0; mt < 2; mt++)
#pragma unroll
                for (int nt = 0; nt < 8; nt++)
                    mma_f16(acc[mt][nt], af[mt], &bf[nt >> 1][(nt & 1) * 2]);

#pragma unroll
            for (int mt = 0; mt < 2; mt++)
                ldmx4(af[mt], uAl + (m_off + mt * 16 + a_r) * ROW_B + kcol2 + a_c * 2);
#pragma unroll
            for (int mt = 0; mt < 2; mt++)
#pragma unroll
                for (int nt = 0; nt < 8; nt++)
                    mma_f16(acc[mt][nt], af[mt], &bf[nt >> 1][(nt & 1) * 2]);
        }
        __syncthreads();
    }

    const int gr  = lid >> 2;
    const int gc2 = (lid & 3) * 2;
#pragma unroll
    for (int mt = 0; mt < 2; mt++) {
#pragma unroll
        for (int nt = 0; nt < 8; nt++) {
            int row0 = bm + m_off + mt * 16 + gr;
            int col  = bn + n_off + nt * 8 + gc2;
            float v0 = acc[mt][nt][0], v1 = acc[mt][nt][1];
            float v2 = acc[mt][nt][2], v3 = acc[mt][nt][3];
            if (MODE == 0) {
                if (do_phi) {
                    v0 = (v0 > 0.f) ? (v0 + 1.f) : expf(v0);
                    v1 = (v1 > 0.f) ? (v1 + 1.f) : expf(v1);
                    v2 = (v2 > 0.f) ? (v2 + 1.f) : expf(v2);
                    v3 = (v3 > 0.f) ? (v3 + 1.f) : expf(v3);
                }
                __half h0 = __float2half(v0), h1 = __float2half(v1);
                __half h2 = __float2half(v2), h3 = __float2half(v3);
                *(__half2*)(oh + (size_t)row0 * EMB + col)       = __halves2half2(h0, h1);
                *(__half2*)(oh + (size_t)(row0 + 8) * EMB + col) = __halves2half2(h2, h3);
                *(__half2*)(ol + (size_t)row0 * EMB + col) =
                    __halves2half2(__float2half(v0 - __half2float(h0)),
                                   __float2half(v1 - __half2float(h1)));
                *(__half2*)(ol + (size_t)(row0 + 8) * EMB + col) =
                    __halves2half2(__float2half(v2 - __half2float(h2)),
                                   __float2half(v3 - __half2float(h3)));
            } else {
                float2 bv = *reinterpret_cast<const float2*>(bias + col);
                *reinterpret_cast<float2*>(Cf + (size_t)row0 * EMB + col) =
                    make_float2(v0 + bv.x, v1 + bv.y);
                *reinterpret_cast<float2*>(Cf + (size_t)(row0 + 8) * EMB + col) =
                    make_float2(v2 + bv.x, v3 + bv.y);
            }
        }
    }
}

// ---------------- Phase A (tensor-core): S_c = k^T v,  z_c = sum_j k ----------------
#define CS_KH 0
#define CS_KL 18432
#define CS_VH 36864
#define CS_VL 55296
#define CS_SMEM 73728

__global__ __launch_bounds__(256)
void chunk_stats_tc(const __half* __restrict__ Kh, const __half* __restrict__ Kl,
                    const __half* __restrict__ Vh, const __half* __restrict__ Vl,
                    float* __restrict__ gS, float* __restrict__ gZ)
{
    extern __shared__ char smem[];
    const uint32_t sb = smem_u32(smem);

    const int blk = blockIdx.x;
    const int c   = blk % NC;
    const int bh  = blk / NC;
    const int b   = bh / NH;
    const int h   = bh % NH;
    const int tid = threadIdx.x;
    const int wid = tid >> 5;
    const int lid = tid & 31;

    const size_t base = ((size_t)(b * TSEQ) + (size_t)c * CHK) * EMB + (size_t)h * HD;

    const __half* srcs[4] = {Kh + base, Kl + base, Vh + base, Vl + base};
    const uint32_t dofs[4] = {CS_KH, CS_KL, CS_VH, CS_VL};
#pragma unroll
    for (int it = 0; it < 16; it++) {
        int idx = tid + it * 256;
        int t = idx >> 10, r = (idx >> 3) & 127, c8 = (idx & 7) * 8;
        uint4 v = *reinterpret_cast<const uint4*>(srcs[t] + (size_t)r * EMB + c8);
        *reinterpret_cast<uint4*>(smem + dofs[t] + r * ROW_B + c8 * 2) = v;
    }
    __syncthreads();

    const int q   = lid >> 3;
    const int a_r = ((q & 1) << 3) + (lid & 7);
    const int a_c = (q >> 1) << 3;
    const int b_r = ((q >> 1) << 3) + (lid & 7);
    const int b_c = (q & 1) << 3;

    const int m_off = (wid & 3) * 16;
    const int n_off = (wid >> 2) * 32;

    float acc[4][4];
#pragma unroll
    for (int nt = 0; nt < 4; nt++)
#pragma unroll
        for (int e = 0; e < 4; e++) acc[nt][e] = 0.f;

#pragma unroll
    for (int ks = 0; ks < 8; ks++) {
        const int jb = ks * 16;
        uint32_t afh[4], afl[4];
        ldmx4t(afh, sb + CS_KH + (jb + b_r) * ROW_B + (m_off + b_c) * 2);
        uint32_t bfh[2][4];
#pragma unroll
        for (int p = 0; p < 2; p++)
            ldmx4t(bfh[p], sb + CS_VH + (jb + a_r) * ROW_B + (n_off + p * 16 + a_c) * 2);
#pragma unroll
        for (int nt = 0; nt < 4; nt++)
            mma_f16(acc[nt], afh, &bfh[nt >> 1][(nt & 1) * 2]);

        uint32_t bfl[2][4];
#pragma unroll
        for (int p = 0; p < 2; p++)
            ldmx4t(bfl[p], sb + CS_VL + (jb + a_r) * ROW_B + (n_off + p * 16 + a_c) * 2);
#pragma unroll
        for (int nt = 0; nt < 4; nt++)
            mma_f16(acc[nt], afh, &bfl[nt >> 1][(nt & 1) * 2]);

        ldmx4t(afl, sb + CS_KL + (jb + b_r) * ROW_B + (m_off + b_c) * 2);
#pragma unroll
        for (int nt = 0; nt < 4; nt++)
            mma_f16(acc[nt], afl, &bfh[nt >> 1][(nt & 1) * 2]);
    }

    const int gr  = lid >> 2;
    const int gc2 = (lid & 3) * 2;
    float* Sout = gS + (size_t)blk * (HD * HD);
#pragma unroll
    for (int nt = 0; nt < 4; nt++) {
        int row0 = m_off + gr;
        int col  = n_off + nt * 8 + gc2;
        *reinterpret_cast<float2*>(Sout + (size_t)row0 * HD + col) =
            make_float2(acc[nt][0], acc[nt][1]);
        *reinterpret_cast<float2*>(Sout + (size_t)(row0 + 8) * HD + col) =
            make_float2(acc[nt][2], acc[nt][3]);
    }

    if (tid < HD) {
        const __half* kh = reinterpret_cast<const __half*>(smem + CS_KH);
        const __half* kl = reinterpret_cast<const __half*>(smem + CS_KL);
        float zsum = 0.f;
        for (int j = 0; j < CHK; j++)
            zsum += __half2float(kh[j * ROW_HALF + tid]) + __half2float(kl[j * ROW_HALF + tid]);
        gZ[(size_t)blk * HD + tid] = zsum;
    }
}

// ---------------- Phase B: exclusive prefix over chunks ----------------
__global__ __launch_bounds__(256)
void prefix_kernel(const float* __restrict__ gS, const float* __restrict__ gZ,
                   float* __restrict__ gSp, float* __restrict__ gZp)
{
    const int bh  = blockIdx.x;
    const int tid = threadIdx.x;

    float acc[16];
#pragma unroll
    for (int i = 0; i < 16; i++) acc[i] = 0.f;

    for (int c = 0; c < NC; c++) {
        size_t off = ((size_t)bh * NC + c) * (HD * HD);
#pragma unroll
        for (int i = 0; i < 16; i++) {
            gSp[off + tid * 16 + i] = acc[i];
            acc[i] += gS[off + tid * 16 + i];
        }
    }
    if (tid < HD) {
        float z = 0.f;
        for (int c = 0; c < NC; c++) {
            size_t off = ((size_t)bh * NC + c) * HD;
            gZp[off + tid] = z;
            z += gZ[off + tid];
        }
    }
}

// ---------------- Phase C: tensor-core per-chunk output ----------------
// P1 3-pass; P3 2-pass (A hi+lo x v_hi; q hi+lo x Sp_hi). No v_lo / Sp_lo in smem.
#define QROWB  144
#define AROWB  272
#define OFF_QH   0
#define OFF_QL   18432
#define OFF_KH   36864
#define OFF_KL   55296
#define OFF_AH   73728
#define OFF_AL   108544
#define OFF_VH   143360
#define OFF_SPH  161792
#define OFF_ZC   171008
#define OFF_DEN  171264
#define OFF_RSP  171776
#define ATTN_SMEM 172800

__global__ __launch_bounds__(256, 1)
void attn_mma_kernel(const __half* __restrict__ Qh_g, const __half* __restrict__ Ql_g,
                     const __half* __restrict__ Kh_g, const __half* __restrict__ Kl_g,
                     const __half* __restrict__ Vh_g,
                     const float* __restrict__ gSp, const float* __restrict__ gZp,
                     __half* __restrict__ Oh, __half* __restrict__ Ol)
{
    extern __shared__ char smem[];
    const uint32_t sb = smem_u32(smem);

    const int blk = blockIdx.x;
    const int c   = blk % NC;
    const int bh  = blk / NC;
    const int b   = bh / NH;
    const int h   = bh % NH;
    const int tid = threadIdx.x;
    const int wid = tid >> 5;
    const int lid = tid & 31;

    const size_t base = ((size_t)(b * TSEQ) + (size_t)c * CHK) * EMB + (size_t)h * HD;

    float* zcs  = reinterpret_cast<float*>(smem + OFF_ZC);
    float* den  = reinterpret_cast<float*>(smem + OFF_DEN);
    float* rsP  = reinterpret_cast<float*>(smem + OFF_RSP);   // [128][2]

    // ---- P0: coalesced fp16 copies (Q,K hi/lo + V hi) + Sp hi convert ----
    {
        const __half* srcs[5] = {Qh_g + base, Ql_g + base, Kh_g + base,
                                 Kl_g + base, Vh_g + base};
        const uint32_t dofs[5] = {OFF_QH, OFF_QL, OFF_KH, OFF_KL, OFF_VH};
#pragma unroll
        for (int it = 0; it < 20; it++) {
            int idx = tid + it * 256;
            int t = idx >> 10, r = (idx >> 3) & 127, c8 = (idx & 7) * 8;
            uint4 v = *reinterpret_cast<const uint4*>(srcs[t] + (size_t)r * EMB + c8);
            *reinterpret_cast<uint4*>(smem + dofs[t] + r * QROWB + c8 * 2) = v;
        }
    }
#pragma unroll
    for (int it = 0; it < 4; it++) {
        int idx = tid + it * 256;                 // 1024 float4 slots
        int d = idx >> 4, e4 = (idx & 15) * 4;
        float4 v = *(const float4*)(gSp + (size_t)blk * (HD * HD) + (size_t)d * HD + e4);
        char* ph = smem + OFF_SPH + d * QROWB + e4 * 2;
        *(__half2*)(ph)     = __floats2half2_rn(v.x, v.y);
        *(__half2*)(ph + 4) = __floats2half2_rn(v.z, v.w);
    }
    if (tid < HD) zcs[tid] = gZp[(size_t)blk * HD + tid];
    __syncthreads();

    const int q   = lid >> 3;
    const int a_r = ((q & 1) << 3) + (lid & 7);
    const int a_c = (q >> 1) << 3;
    const int b_r = ((q >> 1) << 3) + (lid & 7);
    const int b_c = (q & 1) << 3;
    const int gr  = lid >> 2;
    const int gc2 = (lid & 3) * 2;

    // ---- P1: A = q k^T, 3-pass, warp tile 32x64 ----
    {
        const int m_off = (wid & 3) * 32;
        const int n_off = (wid >> 2) * 64;
        const int wn    = wid >> 2;

        float acc[2][8][4];
#pragma unroll
        for (int mt = 0; mt < 2; mt++)
#pragma unroll
            for (int nt = 0; nt < 8; nt++)
#pragma unroll
                for (int e = 0; e < 4; e++) acc[mt][nt][e] = 0.f;

#pragma unroll
        for (int ks = 0; ks < 4; ks++) {
            const int kcol = ks * 32;
            uint32_t bfh[4][4];
#pragma unroll
            for (int p = 0; p < 4; p++)
                ldmx4(bfh[p], sb + OFF_KH + (n_off + p * 16 + b_r) * QROWB + kcol + b_c * 2);
            uint32_t af[2][4];
#pragma unroll
            for (int mt = 0; mt < 2; mt++)
                ldmx4(af[mt], sb + OFF_QH + (m_off + mt * 16 + a_r) * QROWB + kcol + a_c * 2);
#pragma unroll
            for (int mt = 0; mt < 2; mt++)
#pragma unroll
                for (int nt = 0; nt < 8; nt++)
                    mma_f16(acc[mt][nt], af[mt], &bfh[nt >> 1][(nt & 1) * 2]);
            uint32_t bfl[4][4];
#pragma unroll
            for (int p = 0; p < 4; p++)
                ldmx4(bfl[p], sb + OFF_KL + (n_off + p * 16 + b_r) * QROWB + kcol + b_c * 2);
#pragma unroll
            for (int mt = 0; mt < 2; mt++)
#pragma unroll
                for (int nt = 0; nt < 8; nt++)
                    mma_f16(acc[mt][nt], af[mt], &bfl[nt >> 1][(nt & 1) * 2]);
#pragma unroll
            for (int mt = 0; mt < 2; mt++)
                ldmx4(af[mt], sb + OFF_QL + (m_off + mt * 16 + a_r) * QROWB + kcol + a_c * 2);
#pragma unroll
            for (int mt = 0; mt < 2; mt++)
#pragma unroll
                for (int nt = 0; nt < 8; nt++)
                    mma_f16(acc[mt][nt], af[mt], &bfh[nt >> 1][(nt & 1) * 2]);
        }

        // mask + rowsum + hi/lo store of A
#pragma unroll
        for (int mt = 0; mt < 2; mt++) {
            const int r0 = m_off + mt * 16 + gr;
            const int r1 = r0 + 8;
            float s0 = 0.f, s1 = 0.f;
#pragma unroll
            for (int nt = 0; nt < 8; nt++) {
                const int col = n_off + nt * 8 + gc2;
                float c0 = (col     <= r0) ? acc[mt][nt][0] : 0.f;
                float c1 = (col + 1 <= r0) ? acc[mt][nt][1] : 0.f;
                float c2 = (col     <= r1) ? acc[mt][nt][2] : 0.f;
                float c3 = (col + 1 <= r1) ? acc[mt][nt][3] : 0.f;
                s0 += c0 + c1;
                s1 += c2 + c3;
                __half h0 = __float2half(c0), h1 = __float2half(c1);
                __half h2 = __float2half(c2), h3 = __float2half(c3);
                *(__half2*)(smem + OFF_AH + r0 * AROWB + col * 2) = __halves2half2(h0, h1);
                *(__half2*)(smem + OFF_AH + r1 * AROWB + col * 2) = __halves2half2(h2, h3);
                *(__half2*)(smem + OFF_AL + r0 * AROWB + col * 2) =
                    __halves2half2(__float2half(c0 - __half2float(h0)),
                                   __float2half(c1 - __half2float(h1)));
                *(__half2*)(smem + OFF_AL + r1 * AROWB + col * 2) =
                    __halves2half2(__float2half(c2 - __half2float(h2)),
                                   __float2half(c3 - __half2float(h3)));
            }
            s0 += __shfl_xor_sync(0xffffffffu, s0, 1);
            s0 += __shfl_xor_sync(0xffffffffu, s0, 2);
            s1 += __shfl_xor_sync(0xffffffffu, s1, 1);
            s1 += __shfl_xor_sync(0xffffffffu, s1, 2);
            if ((lid & 3) == 0) {
                rsP[r0 * 2 + wn] = s0;
                rsP[r1 * 2 + wn] = s1;
            }
        }
    }
    __syncthreads();

    // ---- P2: den ----
    if (tid < CHK) {
        float rs = rsP[tid * 2 + 0] + rsP[tid * 2 + 1];
        float qz = 0.f;
#pragma unroll
        for (int d = 0; d < HD; d++) {
            float qv = __half2float(*(const __half*)(smem + OFF_QH + tid * QROWB + d * 2))
                     + __half2float(*(const __half*)(smem + OFF_QL + tid * QROWB + d * 2));
            qz += qv * zcs[d];
        }
        den[tid] = rs + qz + EPS_F;
    }

    // ---- P3: num = A@v + q@Sp, 2-pass each, warp tile 32x32 ----
    const int m_off3 = (wid & 3) * 32;
    const int n_off3 = (wid >> 2) * 32;
    float o[2][4][4];
#pragma unroll
    for (int mt = 0; mt < 2; mt++)
#pragma unroll
        for (int nt = 0; nt < 4; nt++)
#pragma unroll
            for (int e = 0; e < 4; e++) o[mt][nt][e] = 0.f;

    // (a) (A_h + A_l) @ v_h : K-dim = 128
#pragma unroll
    for (int ks = 0; ks < 8; ks++) {
        const int jb = ks * 16;
        const int kcol = ks * 32;
        uint32_t bfh[2][4];
#pragma unroll
        for (int p = 0; p < 2; p++)
            ldmx4t(bfh[p], sb + OFF_VH + (jb + a_r) * QROWB + (n_off3 + p * 16 + a_c) * 2);
        uint32_t af[2][4];
#pragma unroll
        for (int mt = 0; mt < 2; mt++)
            ldmx4(af[mt], sb + OFF_AH + (m_off3 + mt * 16 + a_r) * AROWB + kcol + a_c * 2);
#pragma unroll
        for (int mt = 0; mt < 2; mt++)
#pragma unroll
            for (int nt = 0; nt < 4; nt++)
                mma_f16(o[mt][nt], af[mt], &bfh[nt >> 1][(nt & 1) * 2]);
#pragma unroll
        for (int mt = 0; mt < 2; mt++)
            ldmx4(af[mt], sb + OFF_AL + (m_off3 + mt * 16 + a_r) * AROWB + kcol + a_c * 2);
#pragma unroll
        for (int mt = 0; mt < 2; mt++)
#pragma unroll
            for (int nt = 0; nt < 4; nt++)
                mma_f16(o[mt][nt], af[mt], &bfh[nt >> 1][(nt & 1) * 2]);
    }

    // (b) (q_h + q_l) @ Sp_h : K-dim = 64
#pragma unroll
    for (int ks = 0; ks < 4; ks++) {
        const int db = ks * 16;
        const int kcol = ks * 32;
        uint32_t bfh[2][4];
#pragma unroll
        for (int p = 0; p < 2; p++)
            ldmx4t(bfh[p], sb + OFF_SPH + (db + a_r) * QROWB + (n_off3 + p * 16 + a_c) * 2);
        uint32_t af[2][4];
#pragma unroll
        for (int mt = 0; mt < 2; mt++)
            ldmx4(af[mt], sb + OFF_QH + (m_off3 + mt * 16 + a_r) * QROWB + kcol + a_c * 2);
#pragma unroll
        for (int mt = 0; mt < 2; mt++)
#pragma unroll
            for (int nt = 0; nt < 4; nt++)
                mma_f16(o[mt][nt], af[mt], &bfh[nt >> 1][(nt & 1) * 2]);
#pragma unroll
        for (int mt = 0; mt < 2; mt++)
            ldmx4(af[mt], sb + OFF_QL + (m_off3 + mt * 16 + a_r) * QROWB + kcol + a_c * 2);
#pragma unroll
        for (int mt = 0; mt < 2; mt++)
#pragma unroll
            for (int nt = 0; nt < 4; nt++)
                mma_f16(o[mt][nt], af[mt], &bfh[nt >> 1][(nt & 1) * 2]);
    }
    __syncthreads();   // den ready; QH/QL reads done

    // ---- P4: divide by den, stage hi/lo into (reused) QH/QL regions ----
#pragma unroll
    for (int mt = 0; mt < 2; mt++) {
        const int r0 = m_off3 + mt * 16 + gr;
        const int r1 = r0 + 8;
        const float i0 = 1.f / den[r0];
        const float i1 = 1.f / den[r1];
#pragma unroll
        for (int nt = 0; nt < 4; nt++) {
            const int col = n_off3 + nt * 8 + gc2;
            float y0 = o[mt][nt][0] * i0;
            float y1 = o[mt][nt][1] * i0;
            float y2 = o[mt][nt][2] * i1;
            float y3 = o[mt][nt][3] * i1;
            __half h0 = __float2half(y0), h1 = __float2half(y1);
            __half h2 = __float2half(y2), h3 = __float2half(y3);
            *(__half2*)(smem + OFF_QH + r0 * QROWB + col * 2) = __halves2half2(h0, h1);
            *(__half2*)(smem + OFF_QH + r1 * QROWB + col * 2) = __halves2half2(h2, h3);
            *(__half2*)(smem + OFF_QL + r0 * QROWB + col * 2) =
                __halves2half2(__float2half(y0 - __half2float(h0)),
                               __float2half(y1 - __half2float(h1)));
            *(__half2*)(smem + OFF_QL + r1 * QROWB + col * 2) =
                __halves2half2(__float2half(y2 - __half2float(h2)),
                               __float2half(y3 - __half2float(h3)));
        }
    }
    __syncthreads();

    // ---- P5: coalesced global writes of hi/lo output ----
#pragma unroll
    for (int it = 0; it < 8; it++) {
        int idx = tid + it * 256;
        int r = idx >> 4, c4 = (idx & 15) * 4;
        uint2 vh = *(const uint2*)(smem + OFF_QH + r * QROWB + c4 * 2);
        uint2 vl = *(const uint2*)(smem + OFF_QL + r * QROWB + c4 * 2);
        *reinterpret_cast<uint2*>(Oh + base + (size_t)r * EMB + c4) = vh;
        *reinterpret_cast<uint2*>(Ol + base + (size_t)r * EMB + c4) = vl;
    }
}

// ---------------- launch ----------------
extern "C" void kernel_launch(void* const* d_in, const int* in_sizes, int n_in,
                              void* d_out, int out_size)
{
    const float* x  = (const float*)d_in[0];
    const float* Wq = (const float*)d_in[1];
    const float* Wk = (const float*)d_in[2];
    const float* Wv = (const float*)d_in[3];
    const float* Wo = (const float*)d_in[4];
    const float* bo = (const float*)d_in[5];
    float* out = (float*)d_out;
    (void)in_sizes; (void)n_in; (void)out_size;

    float *pS, *pSp, *pZ, *pZp;
    cudaGetSymbolAddress((void**)&pS,  g_S);
    cudaGetSymbolAddress((void**)&pSp, g_Sp);
    cudaGetSymbolAddress((void**)&pZ,  g_z);
    cudaGetSymbolAddress((void**)&pZp, g_zp);

    __half *xh, *xl, *qh_, *ql_, *kh_, *kl_, *vh_, *vl_, *ah, *al, *wh;
    cudaGetSymbolAddress((void**)&xh,  g_xh);
    cudaGetSymbolAddress((void**)&xl,  g_xl);
    cudaGetSymbolAddress((void**)&qh_, g_qh);
    cudaGetSymbolAddress((void**)&ql_, g_ql);
    cudaGetSymbolAddress((void**)&kh_, g_kh);
    cudaGetSymbolAddress((void**)&kl_, g_kl);
    cudaGetSymbolAddress((void**)&vh_, g_vh);
    cudaGetSymbolAddress((void**)&vl_, g_vl);
    cudaGetSymbolAddress((void**)&ah,  g_ah);
    cudaGetSymbolAddress((void**)&al,  g_al);
    cudaGetSymbolAddress((void**)&wh,  g_w);

    cudaFuncSetAttribute(mma_gemm_half<0>,
                         cudaFuncAttributeMaxDynamicSharedMemorySize, GEMM_SMEM);
    cudaFuncSetAttribute(mma_gemm_half<1>,
                         cudaFuncAttributeMaxDynamicSharedMemorySize, GEMM_SMEM);
    cudaFuncSetAttribute(chunk_stats_tc,
                         cudaFuncAttributeMaxDynamicSharedMemorySize, CS_SMEM);
    cudaFuncSetAttribute(attn_mma_kernel,
                         cudaFuncAttributeMaxDynamicSharedMemorySize, ATTN_SMEM);

    const int n4x = MROWS * EMB / 4;   // 1048576
    const int n4w = EMB * EMB / 4;     // 262144

    // operand conversion
    split_half_kernel<<<n4x / 256, 256>>>(x, xh, xl, n4x);
    conv_w_kernel<<<dim3(n4w / 256, 4), 256>>>(Wq, Wk, Wv, Wo, wh);

    // Fused Q/K/V projections -> fp16 hi/lo (phi fused for z<2)
    dim3 qkv_grid(EMB / 128, MROWS / 128, 3);     // (8, 32, 3)
    mma_gemm_half<0><<<qkv_grid, 256, GEMM_SMEM>>>(xh, xl, wh, nullptr, nullptr,
                                                   qh_, ql_, kh_, kl_, vh_, vl_);

    // Chunked recurrent state: tc stats -> prefix -> tc output (emits fp16 hi/lo)
    chunk_stats_tc<<<BATCH * NH * NC, 256, CS_SMEM>>>(kh_, kl_, vh_, vl_, pS, pZ);
    prefix_kernel<<<BATCH * NH, 256>>>(pS, pZ, pSp, pZp);
    attn_mma_kernel<<<BATCH * NH * NC, 256, ATTN_SMEM>>>(qh_, ql_, kh_, kl_, vh_,
                                                         pSp, pZp, ah, al);

    // Output projection + bias (fp32 out)
    dim3 o_grid(EMB / 128, MROWS / 128, 1);
    mma_gemm_half<1><<<o_grid, 256, GEMM_SMEM>>>(ah, al, wh + (size_t)3 * EMB * EMB, bo,
                                                 out, nullptr, nullptr, nullptr,
                                                 nullptr, nullptr, nullptr);
}

// round 16
// speedup vs baseline: 2.6964x; 1.1283x over previous
#include <cuda_runtime.h>
#include <cuda_fp16.h>
#include <cstdint>
#include <cstddef>

// Problem constants (fixed by setup_inputs)
#define BATCH 2
#define TSEQ  2048
#define EMB   1024
#define NH    16
#define HD    64
#define CHK   128
#define NC    (TSEQ / CHK)          // 16
#define MROWS (BATCH * TSEQ)        // 4096
#define EPS_F 1e-5f

// ---------------- scratch (static device allocations) ----------------
__device__ float g_S [(size_t)BATCH * NH * NC * HD * HD];
__device__ float g_Sp[(size_t)BATCH * NH * NC * HD * HD];
__device__ float g_z [(size_t)BATCH * NH * NC * HD];
__device__ float g_zp[(size_t)BATCH * NH * NC * HD];

// fp16 hi/lo operands
__device__ __half g_xh[(size_t)MROWS * EMB];
__device__ __half g_xl[(size_t)MROWS * EMB];
__device__ __half g_qh[(size_t)MROWS * EMB];
__device__ __half g_ql[(size_t)MROWS * EMB];
__device__ __half g_kh[(size_t)MROWS * EMB];
__device__ __half g_kl[(size_t)MROWS * EMB];
__device__ __half g_vh[(size_t)MROWS * EMB];
__device__ __half g_vl[(size_t)MROWS * EMB];
__device__ __half g_ah[(size_t)MROWS * EMB];
__device__ __half g_al[(size_t)MROWS * EMB];
__device__ __half g_w [(size_t)4 * EMB * EMB]; // Wq, Wk, Wv, Wo (fp16)

// ---------------- PTX helpers (arch-agnostic: valid on target sm_103) ----------------
__device__ __forceinline__ uint32_t smem_u32(const void* p) {
    uint32_t a;
    asm("{ .reg .u64 t; cvta.to.shared.u64 t, %1; cvt.u32.u64 %0, t; }"
        : "=r"(a) : "l"(p));
    return a;
}
__device__ __forceinline__ void cp16(uint32_t s, const void* g) {
    asm volatile("cp.async.cg.shared.global [%0], [%1], 16;" :: "r"(s), "l"(g) : "memory");
}
__device__ __forceinline__ void cp_commit() {
    asm volatile("cp.async.commit_group;" ::: "memory");
}
__device__ __forceinline__ void cp_wait0() {
    asm volatile("cp.async.wait_group 0;" ::: "memory");
}
__device__ __forceinline__ void cp_wait1() {
    asm volatile("cp.async.wait_group 1;" ::: "memory");
}
__device__ __forceinline__ void ldmx4(uint32_t* r, uint32_t addr) {
    asm volatile("ldmatrix.sync.aligned.m8n8.x4.shared.b16 {%0,%1,%2,%3}, [%4];"
                 : "=r"(r[0]), "=r"(r[1]), "=r"(r[2]), "=r"(r[3]) : "r"(addr));
}
__device__ __forceinline__ void ldmx4t(uint32_t* r, uint32_t addr) {
    asm volatile("ldmatrix.sync.aligned.m8n8.x4.trans.shared.b16 {%0,%1,%2,%3}, [%4];"
                 : "=r"(r[0]), "=r"(r[1]), "=r"(r[2]), "=r"(r[3]) : "r"(addr));
}
__device__ __forceinline__ void mma_f16(float* c, const uint32_t* a, const uint32_t* b) {
    asm volatile("mma.sync.aligned.m16n8k16.row.col.f32.f16.f16.f32 "
                 "{%0,%1,%2,%3},{%4,%5,%6,%7},{%8,%9},{%0,%1,%2,%3};"
                 : "+f"(c[0]), "+f"(c[1]), "+f"(c[2]), "+f"(c[3])
                 : "r"(a[0]), "r"(a[1]), "r"(a[2]), "r"(a[3]), "r"(b[0]), "r"(b[1]));
}

// ---------------- hi/lo fp16 split (x only) ----------------
__global__ __launch_bounds__(256)
void split_half_kernel(const float* __restrict__ in,
                       __half* __restrict__ hi, __half* __restrict__ lo, int n4)
{
    int i = blockIdx.x * 256 + threadIdx.x;
    if (i >= n4) return;
    float4 v = reinterpret_cast<const float4*>(in)[i];
    __half2 h01 = __floats2half2_rn(v.x, v.y);
    __half2 h23 = __floats2half2_rn(v.z, v.w);
    float2 f01 = __half22float2(h01);
    float2 f23 = __half22float2(h23);
    reinterpret_cast<__half2*>(hi)[2 * i + 0] = h01;
    reinterpret_cast<__half2*>(hi)[2 * i + 1] = h23;
    reinterpret_cast<__half2*>(lo)[2 * i + 0] = __floats2half2_rn(v.x - f01.x, v.y - f01.y);
    reinterpret_cast<__half2*>(lo)[2 * i + 1] = __floats2half2_rn(v.z - f23.x, v.w - f23.y);
}

// ---------------- fp16 convert for all 4 weights (one launch) ----------------
__global__ __launch_bounds__(256)
void conv_w_kernel(const float* __restrict__ Wq, const float* __restrict__ Wk,
                   const float* __restrict__ Wv, const float* __restrict__ Wo,
                   __half* __restrict__ dst)
{
    const int wsel = blockIdx.y;
    const float* src = (wsel == 0) ? Wq : (wsel == 1) ? Wk : (wsel == 2) ? Wv : Wo;
    int i = blockIdx.x * 256 + threadIdx.x;
    float4 v = reinterpret_cast<const float4*>(src)[i];
    __half2* o = reinterpret_cast<__half2*>(dst + (size_t)wsel * EMB * EMB);
    o[2 * i + 0] = __floats2half2_rn(v.x, v.y);
    o[2 * i + 1] = __floats2half2_rn(v.z, v.w);
}

// ---------------- mma.sync fp16 GEMM: C = act( A @ W^T ) ----------------
// MODE 0: fused QKV, emits fp16 hi/lo outputs (phi for z<2).
//         Q,K: 2-pass (A_hi + A_lo). V (z==2): 1-pass (A_hi only) — error
//         enters output linearly, ~2.4e-4 added in quadrature.
// MODE 1: output projection (+bias), emits fp32, 2-pass.
#define KC        64
#define NKC       (EMB / KC)            // 16
#define ROW_HALF  72
#define ROW_B     (ROW_HALF * 2)        // 144
#define TILE_BY   (128 * ROW_B)         // 18432
#define STAGE_BY  (3 * TILE_BY)         // 55296
#define GEMM_SMEM (2 * STAGE_BY)        // 110592

template <int MODE>
__global__ __launch_bounds__(256, 2)
void mma_gemm_half(const __half* __restrict__ Ah, const __half* __restrict__ Al,
                   const __half* __restrict__ Wall, const float* __restrict__ bias,
                   float* __restrict__ Cf,
                   __half* __restrict__ OhQ, __half* __restrict__ OlQ,
                   __half* __restrict__ OhK, __half* __restrict__ OlK,
                   __half* __restrict__ OhV, __half* __restrict__ OlV)
{
    extern __shared__ char smem[];
    const uint32_t sb = smem_u32(smem);

    const int z = (MODE == 0) ? blockIdx.z : 0;
    const __half* B = Wall + (size_t)z * EMB * EMB;
    __half* oh = (z == 0) ? OhQ : (z == 1) ? OhK : OhV;
    __half* ol = (z == 0) ? OlQ : (z == 1) ? OlK : OlV;
    const int do_phi  = (MODE == 0) && (z < 2);
    const bool lo_pass = (MODE == 1) || (z < 2);   // V projection: single pass

    const int tid = threadIdx.x;
    const int wid = tid >> 5;
    const int lid = tid & 31;
    const int bm  = blockIdx.y * 128;
    const int bn  = blockIdx.x * 128;

    const int m_off = (wid & 3) * 32;
    const int n_off = (wid >> 2) * 64;

    const int q   = lid >> 3;
    const int a_r = ((q & 1) << 3) + (lid & 7);
    const int a_c = (q >> 1) << 3;
    const int b_r = ((q >> 1) << 3) + (lid & 7);
    const int b_c = (q & 1) << 3;

    auto load_chunk = [&](int kc, int stg) {
#pragma unroll
        for (int it = 0; it < 12; it++) {
            int idx = tid + it * 256;
            int t = idx >> 10;
            if (t == 1 && !lo_pass) continue;     // skip A_lo tile for V
            int r = (idx >> 3) & 127;
            int c = idx & 7;
            uint32_t saddr = sb + stg * STAGE_BY + t * TILE_BY + r * ROW_B + c * 16;
            const __half* src = (t == 0) ? Ah : (t == 1) ? Al : B;
            int grow = (t < 2) ? (bm + r) : (bn + r);
            cp16(saddr, src + (size_t)grow * EMB + kc * KC + c * 8);
        }
        cp_commit();
    };

    float acc[2][8][4];
#pragma unroll
    for (int mt = 0; mt < 2; mt++)
#pragma unroll
        for (int nt = 0; nt < 8; nt++)
#pragma unroll
            for (int e = 0; e < 4; e++) acc[mt][nt][e] = 0.f;

    load_chunk(0, 0);

    for (int kc = 0; kc < NKC; kc++) {
        if (kc + 1 < NKC) { load_chunk(kc + 1, (kc + 1) & 1); cp_wait1(); }
        else              { cp_wait0(); }
        __syncthreads();

        const uint32_t uAh = sb + (kc & 1) * STAGE_BY;
        const uint32_t uAl = uAh + TILE_BY;
        const uint32_t uB  = uAl + TILE_BY;

#pragma unroll
        for (int ks = 0; ks < 4; ks++) {
            const int kcol2 = ks * 32;

            uint32_t bf[4][4];
#pragma unroll
            for (int p = 0; p < 4; p++)
                ldmx4(bf[p], uB + (n_off + p * 16 + b_r) * ROW_B + kcol2 + b_c * 2);

            uint32_t af[2][4];
#pragma unroll
            for (int mt = 0; mt < 2; mt++)
                ldmx4(af[mt], uAh + (m_off + mt * 16 + a_r) * ROW_B + kcol2 + a_c * 2);
#pragma unroll
            for (int mt = 0; mt < 2; mt++)
#pragma unroll
                for (int nt = 0; nt < 8; nt++)
                    mma_f16(acc[mt][nt], af[mt], &bf[nt >> 1][(nt & 1) * 2]);

            if (lo_pass) {
#pragma unroll
                for (int mt = 0; mt < 2; mt++)
                    ldmx4(af[mt], uAl + (m_off + mt * 16 + a_r) * ROW_B + kcol2 + a_c * 2);
#pragma unroll
                for (int mt = 0; mt < 2; mt++)
#pragma unroll
                    for (int nt = 0; nt < 8; nt++)
                        mma_f16(acc[mt][nt], af[mt], &bf[nt >> 1][(nt & 1) * 2]);
            }
        }
        __syncthreads();
    }

    const int gr  = lid >> 2;
    const int gc2 = (lid & 3) * 2;
#pragma unroll
    for (int mt = 0; mt < 2; mt++) {
#pragma unroll
        for (int nt = 0; nt < 8; nt++) {
            int row0 = bm + m_off + mt * 16 + gr;
            int col  = bn + n_off + nt * 8 + gc2;
            float v0 = acc[mt][nt][0], v1 = acc[mt][nt][1];
            float v2 = acc[mt][nt][2], v3 = acc[mt][nt][3];
            if (MODE == 0) {
                if (do_phi) {
                    v0 = (v0 > 0.f) ? (v0 + 1.f) : expf(v0);
                    v1 = (v1 > 0.f) ? (v1 + 1.f) : expf(v1);
                    v2 = (v2 > 0.f) ? (v2 + 1.f) : expf(v2);
                    v3 = (v3 > 0.f) ? (v3 + 1.f) : expf(v3);
                }
                __half h0 = __float2half(v0), h1 = __float2half(v1);
                __half h2 = __float2half(v2), h3 = __float2half(v3);
                *(__half2*)(oh + (size_t)row0 * EMB + col)       = __halves2half2(h0, h1);
                *(__half2*)(oh + (size_t)(row0 + 8) * EMB + col) = __halves2half2(h2, h3);
                *(__half2*)(ol + (size_t)row0 * EMB + col) =
                    __halves2half2(__float2half(v0 - __half2float(h0)),
                                   __float2half(v1 - __half2float(h1)));
                *(__half2*)(ol + (size_t)(row0 + 8) * EMB + col) =
                    __halves2half2(__float2half(v2 - __half2float(h2)),
                                   __float2half(v3 - __half2float(h3)));
            } else {
                float2 bv = *reinterpret_cast<const float2*>(bias + col);
                *reinterpret_cast<float2*>(Cf + (size_t)row0 * EMB + col) =
                    make_float2(v0 + bv.x, v1 + bv.y);
                *reinterpret_cast<float2*>(Cf + (size_t)(row0 + 8) * EMB + col) =
                    make_float2(v2 + bv.x, v3 + bv.y);
            }
        }
    }
}

// ---------------- Phase A (tensor-core): S_c = k^T v,  z_c = sum_j k ----------------
#define CS_KH 0
#define CS_KL 18432
#define CS_VH 36864
#define CS_VL 55296
#define CS_SMEM 73728

__global__ __launch_bounds__(256)
void chunk_stats_tc(const __half* __restrict__ Kh, const __half* __restrict__ Kl,
                    const __half* __restrict__ Vh, const __half* __restrict__ Vl,
                    float* __restrict__ gS, float* __restrict__ gZ)
{
    extern __shared__ char smem[];
    const uint32_t sb = smem_u32(smem);

    const int blk = blockIdx.x;
    const int c   = blk % NC;
    const int bh  = blk / NC;
    const int b   = bh / NH;
    const int h   = bh % NH;
    const int tid = threadIdx.x;
    const int wid = tid >> 5;
    const int lid = tid & 31;

    const size_t base = ((size_t)(b * TSEQ) + (size_t)c * CHK) * EMB + (size_t)h * HD;

    const __half* srcs[4] = {Kh + base, Kl + base, Vh + base, Vl + base};
    const uint32_t dofs[4] = {CS_KH, CS_KL, CS_VH, CS_VL};
#pragma unroll
    for (int it = 0; it < 16; it++) {
        int idx = tid + it * 256;
        int t = idx >> 10, r = (idx >> 3) & 127, c8 = (idx & 7) * 8;
        uint4 v = *reinterpret_cast<const uint4*>(srcs[t] + (size_t)r * EMB + c8);
        *reinterpret_cast<uint4*>(smem + dofs[t] + r * ROW_B + c8 * 2) = v;
    }
    __syncthreads();

    const int q   = lid >> 3;
    const int a_r = ((q & 1) << 3) + (lid & 7);
    const int a_c = (q >> 1) << 3;
    const int b_r = ((q >> 1) << 3) + (lid & 7);
    const int b_c = (q & 1) << 3;

    const int m_off = (wid & 3) * 16;
    const int n_off = (wid >> 2) * 32;

    float acc[4][4];
#pragma unroll
    for (int nt = 0; nt < 4; nt++)
#pragma unroll
        for (int e = 0; e < 4; e++) acc[nt][e] = 0.f;

#pragma unroll
    for (int ks = 0; ks < 8; ks++) {
        const int jb = ks * 16;
        uint32_t afh[4], afl[4];
        ldmx4t(afh, sb + CS_KH + (jb + b_r) * ROW_B + (m_off + b_c) * 2);
        uint32_t bfh[2][4];
#pragma unroll
        for (int p = 0; p < 2; p++)
            ldmx4t(bfh[p], sb + CS_VH + (jb + a_r) * ROW_B + (n_off + p * 16 + a_c) * 2);
#pragma unroll
        for (int nt = 0; nt < 4; nt++)
            mma_f16(acc[nt], afh, &bfh[nt >> 1][(nt & 1) * 2]);

        uint32_t bfl[2][4];
#pragma unroll
        for (int p = 0; p < 2; p++)
            ldmx4t(bfl[p], sb + CS_VL + (jb + a_r) * ROW_B + (n_off + p * 16 + a_c) * 2);
#pragma unroll
        for (int nt = 0; nt < 4; nt++)
            mma_f16(acc[nt], afh, &bfl[nt >> 1][(nt & 1) * 2]);

        ldmx4t(afl, sb + CS_KL + (jb + b_r) * ROW_B + (m_off + b_c) * 2);
#pragma unroll
        for (int nt = 0; nt < 4; nt++)
            mma_f16(acc[nt], afl, &bfh[nt >> 1][(nt & 1) * 2]);
    }

    const int gr  = lid >> 2;
    const int gc2 = (lid & 3) * 2;
    float* Sout = gS + (size_t)blk * (HD * HD);
#pragma unroll
    for (int nt = 0; nt < 4; nt++) {
        int row0 = m_off + gr;
        int col  = n_off + nt * 8 + gc2;
        *reinterpret_cast<float2*>(Sout + (size_t)row0 * HD + col) =
            make_float2(acc[nt][0], acc[nt][1]);
        *reinterpret_cast<float2*>(Sout + (size_t)(row0 + 8) * HD + col) =
            make_float2(acc[nt][2], acc[nt][3]);
    }

    if (tid < HD) {
        const __half* kh = reinterpret_cast<const __half*>(smem + CS_KH);
        const __half* kl = reinterpret_cast<const __half*>(smem + CS_KL);
        float zsum = 0.f;
        for (int j = 0; j < CHK; j++)
            zsum += __half2float(kh[j * ROW_HALF + tid]) + __half2float(kl[j * ROW_HALF + tid]);
        gZ[(size_t)blk * HD + tid] = zsum;
    }
}

// ---------------- Phase B: exclusive prefix over chunks ----------------
__global__ __launch_bounds__(256)
void prefix_kernel(const float* __restrict__ gS, const float* __restrict__ gZ,
                   float* __restrict__ gSp, float* __restrict__ gZp)
{
    const int bh  = blockIdx.x;
    const int tid = threadIdx.x;

    float acc[16];
#pragma unroll
    for (int i = 0; i < 16; i++) acc[i] = 0.f;

    for (int c = 0; c < NC; c++) {
        size_t off = ((size_t)bh * NC + c) * (HD * HD);
#pragma unroll
        for (int i = 0; i < 16; i++) {
            gSp[off + tid * 16 + i] = acc[i];
            acc[i] += gS[off + tid * 16 + i];
        }
    }
    if (tid < HD) {
        float z = 0.f;
        for (int c = 0; c < NC; c++) {
            size_t off = ((size_t)bh * NC + c) * HD;
            gZp[off + tid] = z;
            z += gZ[off + tid];
        }
    }
}

// ---------------- Phase C: tensor-core per-chunk output ----------------
// P1 3-pass; P3 2-pass (A hi+lo x v_hi; q hi+lo x Sp_hi). No v_lo / Sp_lo in smem.
#define QROWB  144
#define AROWB  272
#define OFF_QH   0
#define OFF_QL   18432
#define OFF_KH   36864
#define OFF_KL   55296
#define OFF_AH   73728
#define OFF_AL   108544
#define OFF_VH   143360
#define OFF_SPH  161792
#define OFF_ZC   171008
#define OFF_DEN  171264
#define OFF_RSP  171776
#define ATTN_SMEM 172800

__global__ __launch_bounds__(256, 1)
void attn_mma_kernel(const __half* __restrict__ Qh_g, const __half* __restrict__ Ql_g,
                     const __half* __restrict__ Kh_g, const __half* __restrict__ Kl_g,
                     const __half* __restrict__ Vh_g,
                     const float* __restrict__ gSp, const float* __restrict__ gZp,
                     __half* __restrict__ Oh, __half* __restrict__ Ol)
{
    extern __shared__ char smem[];
    const uint32_t sb = smem_u32(smem);

    const int blk = blockIdx.x;
    const int c   = blk % NC;
    const int bh  = blk / NC;
    const int b   = bh / NH;
    const int h   = bh % NH;
    const int tid = threadIdx.x;
    const int wid = tid >> 5;
    const int lid = tid & 31;

    const size_t base = ((size_t)(b * TSEQ) + (size_t)c * CHK) * EMB + (size_t)h * HD;

    float* zcs  = reinterpret_cast<float*>(smem + OFF_ZC);
    float* den  = reinterpret_cast<float*>(smem + OFF_DEN);
    float* rsP  = reinterpret_cast<float*>(smem + OFF_RSP);   // [128][2]

    // ---- P0: coalesced fp16 copies (Q,K hi/lo + V hi) + Sp hi convert ----
    {
        const __half* srcs[5] = {Qh_g + base, Ql_g + base, Kh_g + base,
                                 Kl_g + base, Vh_g + base};
        const uint32_t dofs[5] = {OFF_QH, OFF_QL, OFF_KH, OFF_KL, OFF_VH};
#pragma unroll
        for (int it = 0; it < 20; it++) {
            int idx = tid + it * 256;
            int t = idx >> 10, r = (idx >> 3) & 127, c8 = (idx & 7) * 8;
            uint4 v = *reinterpret_cast<const uint4*>(srcs[t] + (size_t)r * EMB + c8);
            *reinterpret_cast<uint4*>(smem + dofs[t] + r * QROWB + c8 * 2) = v;
        }
    }
#pragma unroll
    for (int it = 0; it < 4; it++) {
        int idx = tid + it * 256;                 // 1024 float4 slots
        int d = idx >> 4, e4 = (idx & 15) * 4;
        float4 v = *(const float4*)(gSp + (size_t)blk * (HD * HD) + (size_t)d * HD + e4);
        char* ph = smem + OFF_SPH + d * QROWB + e4 * 2;
        *(__half2*)(ph)     = __floats2half2_rn(v.x, v.y);
        *(__half2*)(ph + 4) = __floats2half2_rn(v.z, v.w);
    }
    if (tid < HD) zcs[tid] = gZp[(size_t)blk * HD + tid];
    __syncthreads();

    const int q   = lid >> 3;
    const int a_r = ((q & 1) << 3) + (lid & 7);
    const int a_c = (q >> 1) << 3;
    const int b_r = ((q >> 1) << 3) + (lid & 7);
    const int b_c = (q & 1) << 3;
    const int gr  = lid >> 2;
    const int gc2 = (lid & 3) * 2;

    // ---- P1: A = q k^T, 3-pass, warp tile 32x64 ----
    {
        const int m_off = (wid & 3) * 32;
        const int n_off = (wid >> 2) * 64;
        const int wn    = wid >> 2;

        float acc[2][8][4];
#pragma unroll
        for (int mt = 0; mt < 2; mt++)
#pragma unroll
            for (int nt = 0; nt < 8; nt++)
#pragma unroll
                for (int e = 0; e < 4; e++) acc[mt][nt][e] = 0.f;

#pragma unroll
        for (int ks = 0; ks < 4; ks++) {
            const int kcol = ks * 32;
            uint32_t bfh[4][4];
#pragma unroll
            for (int p = 0; p < 4; p++)
                ldmx4(bfh[p], sb + OFF_KH + (n_off + p * 16 + b_r) * QROWB + kcol + b_c * 2);
            uint32_t af[2][4];
#pragma unroll
            for (int mt = 0; mt < 2; mt++)
                ldmx4(af[mt], sb + OFF_QH + (m_off + mt * 16 + a_r) * QROWB + kcol + a_c * 2);
#pragma unroll
            for (int mt = 0; mt < 2; mt++)
#pragma unroll
                for (int nt = 0; nt < 8; nt++)
                    mma_f16(acc[mt][nt], af[mt], &bfh[nt >> 1][(nt & 1) * 2]);
            uint32_t bfl[4][4];
#pragma unroll
            for (int p = 0; p < 4; p++)
                ldmx4(bfl[p], sb + OFF_KL + (n_off + p * 16 + b_r) * QROWB + kcol + b_c * 2);
#pragma unroll
            for (int mt = 0; mt < 2; mt++)
#pragma unroll
                for (int nt = 0; nt < 8; nt++)
                    mma_f16(acc[mt][nt], af[mt], &bfl[nt >> 1][(nt & 1) * 2]);
#pragma unroll
            for (int mt = 0; mt < 2; mt++)
                ldmx4(af[mt], sb + OFF_QL + (m_off + mt * 16 + a_r) * QROWB + kcol + a_c * 2);
#pragma unroll
            for (int mt = 0; mt < 2; mt++)
#pragma unroll
                for (int nt = 0; nt < 8; nt++)
                    mma_f16(acc[mt][nt], af[mt], &bfh[nt >> 1][(nt & 1) * 2]);
        }

        // mask + rowsum + hi/lo store of A
#pragma unroll
        for (int mt = 0; mt < 2; mt++) {
            const int r0 = m_off + mt * 16 + gr;
            const int r1 = r0 + 8;
            float s0 = 0.f, s1 = 0.f;
#pragma unroll
            for (int nt = 0; nt < 8; nt++) {
                const int col = n_off + nt * 8 + gc2;
                float c0 = (col     <= r0) ? acc[mt][nt][0] : 0.f;
                float c1 = (col + 1 <= r0) ? acc[mt][nt][1] : 0.f;
                float c2 = (col     <= r1) ? acc[mt][nt][2] : 0.f;
                float c3 = (col + 1 <= r1) ? acc[mt][nt][3] : 0.f;
                s0 += c0 + c1;
                s1 += c2 + c3;
                __half h0 = __float2half(c0), h1 = __float2half(c1);
                __half h2 = __float2half(c2), h3 = __float2half(c3);
                *(__half2*)(smem + OFF_AH + r0 * AROWB + col * 2) = __halves2half2(h0, h1);
                *(__half2*)(smem + OFF_AH + r1 * AROWB + col * 2) = __halves2half2(h2, h3);
                *(__half2*)(smem + OFF_AL + r0 * AROWB + col * 2) =
                    __halves2half2(__float2half(c0 - __half2float(h0)),
                                   __float2half(c1 - __half2float(h1)));
                *(__half2*)(smem + OFF_AL + r1 * AROWB + col * 2) =
                    __halves2half2(__float2half(c2 - __half2float(h2)),
                                   __float2half(c3 - __half2float(h3)));
            }
            s0 += __shfl_xor_sync(0xffffffffu, s0, 1);
            s0 += __shfl_xor_sync(0xffffffffu, s0, 2);
            s1 += __shfl_xor_sync(0xffffffffu, s1, 1);
            s1 += __shfl_xor_sync(0xffffffffu, s1, 2);
            if ((lid & 3) == 0) {
                rsP[r0 * 2 + wn] = s0;
                rsP[r1 * 2 + wn] = s1;
            }
        }
    }
    __syncthreads();

    // ---- P2: den ----
    if (tid < CHK) {
        float rs = rsP[tid * 2 + 0] + rsP[tid * 2 + 1];
        float qz = 0.f;
#pragma unroll
        for (int d = 0; d < HD; d++) {
            float qv = __half2float(*(const __half*)(smem + OFF_QH + tid * QROWB + d * 2))
                     + __half2float(*(const __half*)(smem + OFF_QL + tid * QROWB + d * 2));
            qz += qv * zcs[d];
        }
        den[tid] = rs + qz + EPS_F;
    }

    // ---- P3: num = A@v + q@Sp, 2-pass each, warp tile 32x32 ----
    const int m_off3 = (wid & 3) * 32;
    const int n_off3 = (wid >> 2) * 32;
    float o[2][4][4];
#pragma unroll
    for (int mt = 0; mt < 2; mt++)
#pragma unroll
        for (int nt = 0; nt < 4; nt++)
#pragma unroll
            for (int e = 0; e < 4; e++) o[mt][nt][e] = 0.f;

    // (a) (A_h + A_l) @ v_h : K-dim = 128
#pragma unroll
    for (int ks = 0; ks < 8; ks++) {
        const int jb = ks * 16;
        const int kcol = ks * 32;
        uint32_t bfh[2][4];
#pragma unroll
        for (int p = 0; p < 2; p++)
            ldmx4t(bfh[p], sb + OFF_VH + (jb + a_r) * QROWB + (n_off3 + p * 16 + a_c) * 2);
        uint32_t af[2][4];
#pragma unroll
        for (int mt = 0; mt < 2; mt++)
            ldmx4(af[mt], sb + OFF_AH + (m_off3 + mt * 16 + a_r) * AROWB + kcol + a_c * 2);
#pragma unroll
        for (int mt = 0; mt < 2; mt++)
#pragma unroll
            for (int nt = 0; nt < 4; nt++)
                mma_f16(o[mt][nt], af[mt], &bfh[nt >> 1][(nt & 1) * 2]);
#pragma unroll
        for (int mt = 0; mt < 2; mt++)
            ldmx4(af[mt], sb + OFF_AL + (m_off3 + mt * 16 + a_r) * AROWB + kcol + a_c * 2);
#pragma unroll
        for (int mt = 0; mt < 2; mt++)
#pragma unroll
            for (int nt = 0; nt < 4; nt++)
                mma_f16(o[mt][nt], af[mt], &bfh[nt >> 1][(nt & 1) * 2]);
    }

    // (b) (q_h + q_l) @ Sp_h : K-dim = 64
#pragma unroll
    for (int ks = 0; ks < 4; ks++) {
        const int db = ks * 16;
        const int kcol = ks * 32;
        uint32_t bfh[2][4];
#pragma unroll
        for (int p = 0; p < 2; p++)
            ldmx4t(bfh[p], sb + OFF_SPH + (db + a_r) * QROWB + (n_off3 + p * 16 + a_c) * 2);
        uint32_t af[2][4];
#pragma unroll
        for (int mt = 0; mt < 2; mt++)
            ldmx4(af[mt], sb + OFF_QH + (m_off3 + mt * 16 + a_r) * QROWB + kcol + a_c * 2);
#pragma unroll
        for (int mt = 0; mt < 2; mt++)
#pragma unroll
            for (int nt = 0; nt < 4; nt++)
                mma_f16(o[mt][nt], af[mt], &bfh[nt >> 1][(nt & 1) * 2]);
#pragma unroll
        for (int mt = 0; mt < 2; mt++)
            ldmx4(af[mt], sb + OFF_QL + (m_off3 + mt * 16 + a_r) * QROWB + kcol + a_c * 2);
#pragma unroll
        for (int mt = 0; mt < 2; mt++)
#pragma unroll
            for (int nt = 0; nt < 4; nt++)
                mma_f16(o[mt][nt], af[mt], &bfh[nt >> 1][(nt & 1) * 2]);
    }
    __syncthreads();   // den ready; QH/QL reads done

    // ---- P4: divide by den, stage hi/lo into (reused) QH/QL regions ----
#pragma unroll
    for (int mt = 0; mt < 2; mt++) {
        const int r0 = m_off3 + mt * 16 + gr;
        const int r1 = r0 + 8;
        const float i0 = 1.f / den[r0];
        const float i1 = 1.f / den[r1];
#pragma unroll
        for (int nt = 0; nt < 4; nt++) {
            const int col = n_off3 + nt * 8 + gc2;
            float y0 = o[mt][nt][0] * i0;
            float y1 = o[mt][nt][1] * i0;
            float y2 = o[mt][nt][2] * i1;
            float y3 = o[mt][nt][3] * i1;
            __half h0 = __float2half(y0), h1 = __float2half(y1);
            __half h2 = __float2half(y2), h3 = __float2half(y3);
            *(__half2*)(smem + OFF_QH + r0 * QROWB + col * 2) = __halves2half2(h0, h1);
            *(__half2*)(smem + OFF_QH + r1 * QROWB + col * 2) = __halves2half2(h2, h3);
            *(__half2*)(smem + OFF_QL + r0 * QROWB + col * 2) =
                __halves2half2(__float2half(y0 - __half2float(h0)),
                               __float2half(y1 - __half2float(h1)));
            *(__half2*)(smem + OFF_QL + r1 * QROWB + col * 2) =
                __halves2half2(__float2half(y2 - __half2float(h2)),
                               __float2half(y3 - __half2float(h3)));
        }
    }
    __syncthreads();

    // ---- P5: coalesced global writes of hi/lo output ----
#pragma unroll
    for (int it = 0; it < 8; it++) {
        int idx = tid + it * 256;
        int r = idx >> 4, c4 = (idx & 15) * 4;
        uint2 vh = *(const uint2*)(smem + OFF_QH + r * QROWB + c4 * 2);
        uint2 vl = *(const uint2*)(smem + OFF_QL + r * QROWB + c4 * 2);
        *reinterpret_cast<uint2*>(Oh + base + (size_t)r * EMB + c4) = vh;
        *reinterpret_cast<uint2*>(Ol + base + (size_t)r * EMB + c4) = vl;
    }
}

// ---------------- launch ----------------
extern "C" void kernel_launch(void* const* d_in, const int* in_sizes, int n_in,
                              void* d_out, int out_size)
{
    const float* x  = (const float*)d_in[0];
    const float* Wq = (const float*)d_in[1];
    const float* Wk = (const float*)d_in[2];
    const float* Wv = (const float*)d_in[3];
    const float* Wo = (const float*)d_in[4];
    const float* bo = (const float*)d_in[5];
    float* out = (float*)d_out;
    (void)in_sizes; (void)n_in; (void)out_size;

    float *pS, *pSp, *pZ, *pZp;
    cudaGetSymbolAddress((void**)&pS,  g_S);
    cudaGetSymbolAddress((void**)&pSp, g_Sp);
    cudaGetSymbolAddress((void**)&pZ,  g_z);
    cudaGetSymbolAddress((void**)&pZp, g_zp);

    __half *xh, *xl, *qh_, *ql_, *kh_, *kl_, *vh_, *vl_, *ah, *al, *wh;
    cudaGetSymbolAddress((void**)&xh,  g_xh);
    cudaGetSymbolAddress((void**)&xl,  g_xl);
    cudaGetSymbolAddress((void**)&qh_, g_qh);
    cudaGetSymbolAddress((void**)&ql_, g_ql);
    cudaGetSymbolAddress((void**)&kh_, g_kh);
    cudaGetSymbolAddress((void**)&kl_, g_kl);
    cudaGetSymbolAddress((void**)&vh_, g_vh);
    cudaGetSymbolAddress((void**)&vl_, g_vl);
    cudaGetSymbolAddress((void**)&ah,  g_ah);
    cudaGetSymbolAddress((void**)&al,  g_al);
    cudaGetSymbolAddress((void**)&wh,  g_w);

    cudaFuncSetAttribute(mma_gemm_half<0>,
                         cudaFuncAttributeMaxDynamicSharedMemorySize, GEMM_SMEM);
    cudaFuncSetAttribute(mma_gemm_half<1>,
                         cudaFuncAttributeMaxDynamicSharedMemorySize, GEMM_SMEM);
    cudaFuncSetAttribute(chunk_stats_tc,
                         cudaFuncAttributeMaxDynamicSharedMemorySize, CS_SMEM);
    cudaFuncSetAttribute(attn_mma_kernel,
                         cudaFuncAttributeMaxDynamicSharedMemorySize, ATTN_SMEM);

    const int n4x = MROWS * EMB / 4;   // 1048576
    const int n4w = EMB * EMB / 4;     // 262144

    // operand conversion
    split_half_kernel<<<n4x / 256, 256>>>(x, xh, xl, n4x);
    conv_w_kernel<<<dim3(n4w / 256, 4), 256>>>(Wq, Wk, Wv, Wo, wh);

    // Fused Q/K/V projections -> fp16 hi/lo (phi fused for z<2; V 1-pass)
    dim3 qkv_grid(EMB / 128, MROWS / 128, 3);     // (8, 32, 3)
    mma_gemm_half<0><<<qkv_grid, 256, GEMM_SMEM>>>(xh, xl, wh, nullptr, nullptr,
                                                   qh_, ql_, kh_, kl_, vh_, vl_);

    // Chunked recurrent state: tc stats -> prefix -> tc output (emits fp16 hi/lo)
    chunk_stats_tc<<<BATCH * NH * NC, 256, CS_SMEM>>>(kh_, kl_, vh_, vl_, pS, pZ);
    prefix_kernel<<<BATCH * NH, 256>>>(pS, pZ, pSp, pZp);
    attn_mma_kernel<<<BATCH * NH * NC, 256, ATTN_SMEM>>>(qh_, ql_, kh_, kl_, vh_,
                                                         pSp, pZp, ah, al);

    // Output projection + bias (fp32 out)
    dim3 o_grid(EMB / 128, MROWS / 128, 1);
    mma_gemm_half<1><<<o_grid, 256, GEMM_SMEM>>>(ah, al, wh + (size_t)3 * EMB * EMB, bo,
                                                 out, nullptr, nullptr, nullptr,
                                                 nullptr, nullptr, nullptr);
}

// round 17
// speedup vs baseline: 3.3737x; 1.2512x over previous
#include <cuda_runtime.h>
#include <cuda_fp16.h>
#include <cstdint>
#include <cstddef>

// Problem constants (fixed by setup_inputs)
#define BATCH 2
#define TSEQ  2048
#define EMB   1024
#define NH    16
#define HD    64
#define CHK   128
#define NC    (TSEQ / CHK)          // 16
#define MROWS (BATCH * TSEQ)        // 4096
#define EPS_F 1e-5f

// ---------------- scratch (static device allocations) ----------------
__device__ float g_S [(size_t)BATCH * NH * NC * HD * HD];
__device__ float g_Sp[(size_t)BATCH * NH * NC * HD * HD];
__device__ float g_z [(size_t)BATCH * NH * NC * HD];
__device__ float g_zp[(size_t)BATCH * NH * NC * HD];

// fp16 operands
__device__ __half g_xh[(size_t)MROWS * EMB];
__device__ __half g_qh[(size_t)MROWS * EMB];
__device__ __half g_ql[(size_t)MROWS * EMB];
__device__ __half g_kh[(size_t)MROWS * EMB];
__device__ __half g_kl[(size_t)MROWS * EMB];
__device__ __half g_vh[(size_t)MROWS * EMB];
__device__ __half g_vl[(size_t)MROWS * EMB];
__device__ __half g_ah[(size_t)MROWS * EMB];
__device__ __half g_w [(size_t)4 * EMB * EMB]; // Wq, Wk, Wv, Wo (fp16)

// ---------------- PTX helpers (arch-agnostic: valid on target sm_103) ----------------
__device__ __forceinline__ uint32_t smem_u32(const void* p) {
    uint32_t a;
    asm("{ .reg .u64 t; cvta.to.shared.u64 t, %1; cvt.u32.u64 %0, t; }"
        : "=r"(a) : "l"(p));
    return a;
}
__device__ __forceinline__ void cp16(uint32_t s, const void* g) {
    asm volatile("cp.async.cg.shared.global [%0], [%1], 16;" :: "r"(s), "l"(g) : "memory");
}
__device__ __forceinline__ void cp_commit() {
    asm volatile("cp.async.commit_group;" ::: "memory");
}
__device__ __forceinline__ void cp_wait0() {
    asm volatile("cp.async.wait_group 0;" ::: "memory");
}
__device__ __forceinline__ void cp_wait1() {
    asm volatile("cp.async.wait_group 1;" ::: "memory");
}
__device__ __forceinline__ void ldmx4(uint32_t* r, uint32_t addr) {
    asm volatile("ldmatrix.sync.aligned.m8n8.x4.shared.b16 {%0,%1,%2,%3}, [%4];"
                 : "=r"(r[0]), "=r"(r[1]), "=r"(r[2]), "=r"(r[3]) : "r"(addr));
}
__device__ __forceinline__ void ldmx4t(uint32_t* r, uint32_t addr) {
    asm volatile("ldmatrix.sync.aligned.m8n8.x4.trans.shared.b16 {%0,%1,%2,%3}, [%4];"
                 : "=r"(r[0]), "=r"(r[1]), "=r"(r[2]), "=r"(r[3]) : "r"(addr));
}
__device__ __forceinline__ void mma_f16(float* c, const uint32_t* a, const uint32_t* b) {
    asm volatile("mma.sync.aligned.m16n8k16.row.col.f32.f16.f16.f32 "
                 "{%0,%1,%2,%3},{%4,%5,%6,%7},{%8,%9},{%0,%1,%2,%3};"
                 : "+f"(c[0]), "+f"(c[1]), "+f"(c[2]), "+f"(c[3])
                 : "r"(a[0]), "r"(a[1]), "r"(a[2]), "r"(a[3]), "r"(b[0]), "r"(b[1]));
}

// ---------------- fp16 convert (x) ----------------
__global__ __launch_bounds__(256)
void conv_x_kernel(const float* __restrict__ in, __half* __restrict__ hi, int n4)
{
    int i = blockIdx.x * 256 + threadIdx.x;
    if (i >= n4) return;
    float4 v = reinterpret_cast<const float4*>(in)[i];
    reinterpret_cast<__half2*>(hi)[2 * i + 0] = __floats2half2_rn(v.x, v.y);
    reinterpret_cast<__half2*>(hi)[2 * i + 1] = __floats2half2_rn(v.z, v.w);
}

// ---------------- fp16 convert for all 4 weights (one launch) ----------------
__global__ __launch_bounds__(256)
void conv_w_kernel(const float* __restrict__ Wq, const float* __restrict__ Wk,
                   const float* __restrict__ Wv, const float* __restrict__ Wo,
                   __half* __restrict__ dst)
{
    const int wsel = blockIdx.y;
    const float* src = (wsel == 0) ? Wq : (wsel == 1) ? Wk : (wsel == 2) ? Wv : Wo;
    int i = blockIdx.x * 256 + threadIdx.x;
    float4 v = reinterpret_cast<const float4*>(src)[i];
    __half2* o = reinterpret_cast<__half2*>(dst + (size_t)wsel * EMB * EMB);
    o[2 * i + 0] = __floats2half2_rn(v.x, v.y);
    o[2 * i + 1] = __floats2half2_rn(v.z, v.w);
}

// ---------------- mma.sync fp16 1-pass GEMM: C = act( A @ W^T ) ----------------
// MODE 0: fused QKV, emits fp16 hi/lo outputs (phi for z<2)
// MODE 1: output projection (+bias), emits fp32
#define KC        64
#define NKC       (EMB / KC)            // 16
#define ROW_HALF  72
#define ROW_B     (ROW_HALF * 2)        // 144
#define TILE_BY   (128 * ROW_B)         // 18432
#define STAGE_BY  (2 * TILE_BY)         // 36864 (Ah, B)
#define GEMM_SMEM (2 * STAGE_BY)        // 73728

template <int MODE>
__global__ __launch_bounds__(256, 2)
void mma_gemm_half(const __half* __restrict__ Ah,
                   const __half* __restrict__ Wall, const float* __restrict__ bias,
                   float* __restrict__ Cf,
                   __half* __restrict__ OhQ, __half* __restrict__ OlQ,
                   __half* __restrict__ OhK, __half* __restrict__ OlK,
                   __half* __restrict__ OhV, __half* __restrict__ OlV)
{
    extern __shared__ char smem[];
    const uint32_t sb = smem_u32(smem);

    const int z = (MODE == 0) ? blockIdx.z : 0;
    const __half* B = Wall + (size_t)z * EMB * EMB;
    __half* oh = (z == 0) ? OhQ : (z == 1) ? OhK : OhV;
    __half* ol = (z == 0) ? OlQ : (z == 1) ? OlK : OlV;
    const int do_phi = (MODE == 0) && (z < 2);

    const int tid = threadIdx.x;
    const int wid = tid >> 5;
    const int lid = tid & 31;
    const int bm  = blockIdx.y * 128;
    const int bn  = blockIdx.x * 128;

    const int m_off = (wid & 3) * 32;
    const int n_off = (wid >> 2) * 64;

    const int q   = lid >> 3;
    const int a_r = ((q & 1) << 3) + (lid & 7);
    const int a_c = (q >> 1) << 3;
    const int b_r = ((q >> 1) << 3) + (lid & 7);
    const int b_c = (q & 1) << 3;

    auto load_chunk = [&](int kc, int stg) {
#pragma unroll
        for (int it = 0; it < 8; it++) {
            int idx = tid + it * 256;             // 2048 16B vectors (2 tiles)
            int t = idx >> 10;                    // 0: Ah, 1: B
            int r = (idx >> 3) & 127;
            int c = idx & 7;
            uint32_t saddr = sb + stg * STAGE_BY + t * TILE_BY + r * ROW_B + c * 16;
            const __half* src = (t == 0) ? Ah : B;
            int grow = (t == 0) ? (bm + r) : (bn + r);
            cp16(saddr, src + (size_t)grow * EMB + kc * KC + c * 8);
        }
        cp_commit();
    };

    float acc[2][8][4];
#pragma unroll
    for (int mt = 0; mt < 2; mt++)
#pragma unroll
        for (int nt = 0; nt < 8; nt++)
#pragma unroll
            for (int e = 0; e < 4; e++) acc[mt][nt][e] = 0.f;

    load_chunk(0, 0);

    for (int kc = 0; kc < NKC; kc++) {
        if (kc + 1 < NKC) { load_chunk(kc + 1, (kc + 1) & 1); cp_wait1(); }
        else              { cp_wait0(); }
        __syncthreads();

        const uint32_t uAh = sb + (kc & 1) * STAGE_BY;
        const uint32_t uB  = uAh + TILE_BY;

#pragma unroll
        for (int ks = 0; ks < 4; ks++) {
            const int kcol2 = ks * 32;

            uint32_t bf[4][4];
#pragma unroll
            for (int p = 0; p < 4; p++)
                ldmx4(bf[p], uB + (n_off + p * 16 + b_r) * ROW_B + kcol2 + b_c * 2);

            uint32_t af[2][4];
#pragma unroll
            for (int mt = 0; mt < 2; mt++)
                ldmx4(af[mt], uAh + (m_off + mt * 16 + a_r) * ROW_B + kcol2 + a_c * 2);
#pragma unroll
            for (int mt = 0; mt < 2; mt++)
#pragma unroll
                for (int nt = 0; nt < 8; nt++)
                    mma_f16(acc[mt][nt], af[mt], &bf[nt >> 1][(nt & 1) * 2]);
        }
        __syncthreads();
    }

    const int gr  = lid >> 2;
    const int gc2 = (lid & 3) * 2;
#pragma unroll
    for (int mt = 0; mt < 2; mt++) {
#pragma unroll
        for (int nt = 0; nt < 8; nt++) {
            int row0 = bm + m_off + mt * 16 + gr;
            int col  = bn + n_off + nt * 8 + gc2;
            float v0 = acc[mt][nt][0], v1 = acc[mt][nt][1];
            float v2 = acc[mt][nt][2], v3 = acc[mt][nt][3];
            if (MODE == 0) {
                if (do_phi) {
                    v0 = (v0 > 0.f) ? (v0 + 1.f) : expf(v0);
                    v1 = (v1 > 0.f) ? (v1 + 1.f) : expf(v1);
                    v2 = (v2 > 0.f) ? (v2 + 1.f) : expf(v2);
                    v3 = (v3 > 0.f) ? (v3 + 1.f) : expf(v3);
                }
                __half h0 = __float2half(v0), h1 = __float2half(v1);
                __half h2 = __float2half(v2), h3 = __float2half(v3);
                *(__half2*)(oh + (size_t)row0 * EMB + col)       = __halves2half2(h0, h1);
                *(__half2*)(oh + (size_t)(row0 + 8) * EMB + col) = __halves2half2(h2, h3);
                *(__half2*)(ol + (size_t)row0 * EMB + col) =
                    __halves2half2(__float2half(v0 - __half2float(h0)),
                                   __float2half(v1 - __half2float(h1)));
                *(__half2*)(ol + (size_t)(row0 + 8) * EMB + col) =
                    __halves2half2(__float2half(v2 - __half2float(h2)),
                                   __float2half(v3 - __half2float(h3)));
            } else {
                float2 bv = *reinterpret_cast<const float2*>(bias + col);
                *reinterpret_cast<float2*>(Cf + (size_t)row0 * EMB + col) =
                    make_float2(v0 + bv.x, v1 + bv.y);
                *reinterpret_cast<float2*>(Cf + (size_t)(row0 + 8) * EMB + col) =
                    make_float2(v2 + bv.x, v3 + bv.y);
            }
        }
    }
}

// ---------------- Phase A (tensor-core): S_c = k^T v,  z_c = sum_j k ----------------
#define CS_KH 0
#define CS_KL 18432
#define CS_VH 36864
#define CS_VL 55296
#define CS_SMEM 73728

__global__ __launch_bounds__(256)
void chunk_stats_tc(const __half* __restrict__ Kh, const __half* __restrict__ Kl,
                    const __half* __restrict__ Vh, const __half* __restrict__ Vl,
                    float* __restrict__ gS, float* __restrict__ gZ)
{
    extern __shared__ char smem[];
    const uint32_t sb = smem_u32(smem);

    const int blk = blockIdx.x;
    const int c   = blk % NC;
    const int bh  = blk / NC;
    const int b   = bh / NH;
    const int h   = bh % NH;
    const int tid = threadIdx.x;
    const int wid = tid >> 5;
    const int lid = tid & 31;

    const size_t base = ((size_t)(b * TSEQ) + (size_t)c * CHK) * EMB + (size_t)h * HD;

    const __half* srcs[4] = {Kh + base, Kl + base, Vh + base, Vl + base};
    const uint32_t dofs[4] = {CS_KH, CS_KL, CS_VH, CS_VL};
#pragma unroll
    for (int it = 0; it < 16; it++) {
        int idx = tid + it * 256;
        int t = idx >> 10, r = (idx >> 3) & 127, c8 = (idx & 7) * 8;
        uint4 v = *reinterpret_cast<const uint4*>(srcs[t] + (size_t)r * EMB + c8);
        *reinterpret_cast<uint4*>(smem + dofs[t] + r * ROW_B + c8 * 2) = v;
    }
    __syncthreads();

    const int q   = lid >> 3;
    const int a_r = ((q & 1) << 3) + (lid & 7);
    const int a_c = (q >> 1) << 3;
    const int b_r = ((q >> 1) << 3) + (lid & 7);
    const int b_c = (q & 1) << 3;

    const int m_off = (wid & 3) * 16;
    const int n_off = (wid >> 2) * 32;

    float acc[4][4];
#pragma unroll
    for (int nt = 0; nt < 4; nt++)
#pragma unroll
        for (int e = 0; e < 4; e++) acc[nt][e] = 0.f;

#pragma unroll
    for (int ks = 0; ks < 8; ks++) {
        const int jb = ks * 16;
        uint32_t afh[4], afl[4];
        ldmx4t(afh, sb + CS_KH + (jb + b_r) * ROW_B + (m_off + b_c) * 2);
        uint32_t bfh[2][4];
#pragma unroll
        for (int p = 0; p < 2; p++)
            ldmx4t(bfh[p], sb + CS_VH + (jb + a_r) * ROW_B + (n_off + p * 16 + a_c) * 2);
#pragma unroll
        for (int nt = 0; nt < 4; nt++)
            mma_f16(acc[nt], afh, &bfh[nt >> 1][(nt & 1) * 2]);

        uint32_t bfl[2][4];
#pragma unroll
        for (int p = 0; p < 2; p++)
            ldmx4t(bfl[p], sb + CS_VL + (jb + a_r) * ROW_B + (n_off + p * 16 + a_c) * 2);
#pragma unroll
        for (int nt = 0; nt < 4; nt++)
            mma_f16(acc[nt], afh, &bfl[nt >> 1][(nt & 1) * 2]);

        ldmx4t(afl, sb + CS_KL + (jb + b_r) * ROW_B + (m_off + b_c) * 2);
#pragma unroll
        for (int nt = 0; nt < 4; nt++)
            mma_f16(acc[nt], afl, &bfh[nt >> 1][(nt & 1) * 2]);
    }

    const int gr  = lid >> 2;
    const int gc2 = (lid & 3) * 2;
    float* Sout = gS + (size_t)blk * (HD * HD);
#pragma unroll
    for (int nt = 0; nt < 4; nt++) {
        int row0 = m_off + gr;
        int col  = n_off + nt * 8 + gc2;
        *reinterpret_cast<float2*>(Sout + (size_t)row0 * HD + col) =
            make_float2(acc[nt][0], acc[nt][1]);
        *reinterpret_cast<float2*>(Sout + (size_t)(row0 + 8) * HD + col) =
            make_float2(acc[nt][2], acc[nt][3]);
    }

    if (tid < HD) {
        const __half* kh = reinterpret_cast<const __half*>(smem + CS_KH);
        const __half* kl = reinterpret_cast<const __half*>(smem + CS_KL);
        float zsum = 0.f;
        for (int j = 0; j < CHK; j++)
            zsum += __half2float(kh[j * ROW_HALF + tid]) + __half2float(kl[j * ROW_HALF + tid]);
        gZ[(size_t)blk * HD + tid] = zsum;
    }
}

// ---------------- Phase B: exclusive prefix over chunks ----------------
__global__ __launch_bounds__(256)
void prefix_kernel(const float* __restrict__ gS, const float* __restrict__ gZ,
                   float* __restrict__ gSp, float* __restrict__ gZp)
{
    const int bh  = blockIdx.x;
    const int tid = threadIdx.x;

    float acc[16];
#pragma unroll
    for (int i = 0; i < 16; i++) acc[i] = 0.f;

    for (int c = 0; c < NC; c++) {
        size_t off = ((size_t)bh * NC + c) * (HD * HD);
#pragma unroll
        for (int i = 0; i < 16; i++) {
            gSp[off + tid * 16 + i] = acc[i];
            acc[i] += gS[off + tid * 16 + i];
        }
    }
    if (tid < HD) {
        float z = 0.f;
        for (int c = 0; c < NC; c++) {
            size_t off = ((size_t)bh * NC + c) * HD;
            gZp[off + tid] = z;
            z += gZ[off + tid];
        }
    }
}

// ---------------- Phase C: tensor-core per-chunk output ----------------
// P1 3-pass; P3 2-pass. Output: fp16 hi only (O-proj is 1-pass).
#define QROWB  144
#define AROWB  272
#define OFF_QH   0
#define OFF_QL   18432
#define OFF_KH   36864
#define OFF_KL   55296
#define OFF_AH   73728
#define OFF_AL   108544
#define OFF_VH   143360
#define OFF_SPH  161792
#define OFF_ZC   171008
#define OFF_DEN  171264
#define OFF_RSP  171776
#define ATTN_SMEM 172800

__global__ __launch_bounds__(256, 1)
void attn_mma_kernel(const __half* __restrict__ Qh_g, const __half* __restrict__ Ql_g,
                     const __half* __restrict__ Kh_g, const __half* __restrict__ Kl_g,
                     const __half* __restrict__ Vh_g,
                     const float* __restrict__ gSp, const float* __restrict__ gZp,
                     __half* __restrict__ Oh)
{
    extern __shared__ char smem[];
    const uint32_t sb = smem_u32(smem);

    const int blk = blockIdx.x;
    const int c   = blk % NC;
    const int bh  = blk / NC;
    const int b   = bh / NH;
    const int h   = bh % NH;
    const int tid = threadIdx.x;
    const int wid = tid >> 5;
    const int lid = tid & 31;

    const size_t base = ((size_t)(b * TSEQ) + (size_t)c * CHK) * EMB + (size_t)h * HD;

    float* zcs  = reinterpret_cast<float*>(smem + OFF_ZC);
    float* den  = reinterpret_cast<float*>(smem + OFF_DEN);
    float* rsP  = reinterpret_cast<float*>(smem + OFF_RSP);   // [128][2]

    // ---- P0: coalesced fp16 copies (Q,K hi/lo + V hi) + Sp hi convert ----
    {
        const __half* srcs[5] = {Qh_g + base, Ql_g + base, Kh_g + base,
                                 Kl_g + base, Vh_g + base};
        const uint32_t dofs[5] = {OFF_QH, OFF_QL, OFF_KH, OFF_KL, OFF_VH};
#pragma unroll
        for (int it = 0; it < 20; it++) {
            int idx = tid + it * 256;
            int t = idx >> 10, r = (idx >> 3) & 127, c8 = (idx & 7) * 8;
            uint4 v = *reinterpret_cast<const uint4*>(srcs[t] + (size_t)r * EMB + c8);
            *reinterpret_cast<uint4*>(smem + dofs[t] + r * QROWB + c8 * 2) = v;
        }
    }
#pragma unroll
    for (int it = 0; it < 4; it++) {
        int idx = tid + it * 256;                 // 1024 float4 slots
        int d = idx >> 4, e4 = (idx & 15) * 4;
        float4 v = *(const float4*)(gSp + (size_t)blk * (HD * HD) + (size_t)d * HD + e4);
        char* ph = smem + OFF_SPH + d * QROWB + e4 * 2;
        *(__half2*)(ph)     = __floats2half2_rn(v.x, v.y);
        *(__half2*)(ph + 4) = __floats2half2_rn(v.z, v.w);
    }
    if (tid < HD) zcs[tid] = gZp[(size_t)blk * HD + tid];
    __syncthreads();

    const int q   = lid >> 3;
    const int a_r = ((q & 1) << 3) + (lid & 7);
    const int a_c = (q >> 1) << 3;
    const int b_r = ((q >> 1) << 3) + (lid & 7);
    const int b_c = (q & 1) << 3;
    const int gr  = lid >> 2;
    const int gc2 = (lid & 3) * 2;

    // ---- P1: A = q k^T, 3-pass, warp tile 32x64 ----
    {
        const int m_off = (wid & 3) * 32;
        const int n_off = (wid >> 2) * 64;
        const int wn    = wid >> 2;

        float acc[2][8][4];
#pragma unroll
        for (int mt = 0; mt < 2; mt++)
#pragma unroll
            for (int nt = 0; nt < 8; nt++)
#pragma unroll
                for (int e = 0; e < 4; e++) acc[mt][nt][e] = 0.f;

#pragma unroll
        for (int ks = 0; ks < 4; ks++) {
            const int kcol = ks * 32;
            uint32_t bfh[4][4];
#pragma unroll
            for (int p = 0; p < 4; p++)
                ldmx4(bfh[p], sb + OFF_KH + (n_off + p * 16 + b_r) * QROWB + kcol + b_c * 2);
            uint32_t af[2][4];
#pragma unroll
            for (int mt = 0; mt < 2; mt++)
                ldmx4(af[mt], sb + OFF_QH + (m_off + mt * 16 + a_r) * QROWB + kcol + a_c * 2);
#pragma unroll
            for (int mt = 0; mt < 2; mt++)
#pragma unroll
                for (int nt = 0; nt < 8; nt++)
                    mma_f16(acc[mt][nt], af[mt], &bfh[nt >> 1][(nt & 1) * 2]);
            uint32_t bfl[4][4];
#pragma unroll
            for (int p = 0; p < 4; p++)
                ldmx4(bfl[p], sb + OFF_KL + (n_off + p * 16 + b_r) * QROWB + kcol + b_c * 2);
#pragma unroll
            for (int mt = 0; mt < 2; mt++)
#pragma unroll
                for (int nt = 0; nt < 8; nt++)
                    mma_f16(acc[mt][nt], af[mt], &bfl[nt >> 1][(nt & 1) * 2]);
#pragma unroll
            for (int mt = 0; mt < 2; mt++)
                ldmx4(af[mt], sb + OFF_QL + (m_off + mt * 16 + a_r) * QROWB + kcol + a_c * 2);
#pragma unroll
            for (int mt = 0; mt < 2; mt++)
#pragma unroll
                for (int nt = 0; nt < 8; nt++)
                    mma_f16(acc[mt][nt], af[mt], &bfh[nt >> 1][(nt & 1) * 2]);
        }

        // mask + rowsum + hi/lo store of A
#pragma unroll
        for (int mt = 0; mt < 2; mt++) {
            const int r0 = m_off + mt * 16 + gr;
            const int r1 = r0 + 8;
            float s0 = 0.f, s1 = 0.f;
#pragma unroll
            for (int nt = 0; nt < 8; nt++) {
                const int col = n_off + nt * 8 + gc2;
                float c0 = (col     <= r0) ? acc[mt][nt][0] : 0.f;
                float c1 = (col + 1 <= r0) ? acc[mt][nt][1] : 0.f;
                float c2 = (col     <= r1) ? acc[mt][nt][2] : 0.f;
                float c3 = (col + 1 <= r1) ? acc[mt][nt][3] : 0.f;
                s0 += c0 + c1;
                s1 += c2 + c3;
                __half h0 = __float2half(c0), h1 = __float2half(c1);
                __half h2 = __float2half(c2), h3 = __float2half(c3);
                *(__half2*)(smem + OFF_AH + r0 * AROWB + col * 2) = __halves2half2(h0, h1);
                *(__half2*)(smem + OFF_AH + r1 * AROWB + col * 2) = __halves2half2(h2, h3);
                *(__half2*)(smem + OFF_AL + r0 * AROWB + col * 2) =
                    __halves2half2(__float2half(c0 - __half2float(h0)),
                                   __float2half(c1 - __half2float(h1)));
                *(__half2*)(smem + OFF_AL + r1 * AROWB + col * 2) =
                    __halves2half2(__float2half(c2 - __half2float(h2)),
                                   __float2half(c3 - __half2float(h3)));
            }
            s0 += __shfl_xor_sync(0xffffffffu, s0, 1);
            s0 += __shfl_xor_sync(0xffffffffu, s0, 2);
            s1 += __shfl_xor_sync(0xffffffffu, s1, 1);
            s1 += __shfl_xor_sync(0xffffffffu, s1, 2);
            if ((lid & 3) == 0) {
                rsP[r0 * 2 + wn] = s0;
                rsP[r1 * 2 + wn] = s1;
            }
        }
    }
    __syncthreads();

    // ---- P2: den ----
    if (tid < CHK) {
        float rs = rsP[tid * 2 + 0] + rsP[tid * 2 + 1];
        float qz = 0.f;
#pragma unroll
        for (int d = 0; d < HD; d++) {
            float qv = __half2float(*(const __half*)(smem + OFF_QH + tid * QROWB + d * 2))
                     + __half2float(*(const __half*)(smem + OFF_QL + tid * QROWB + d * 2));
            qz += qv * zcs[d];
        }
        den[tid] = rs + qz + EPS_F;
    }

    // ---- P3: num = A@v + q@Sp, 2-pass each, warp tile 32x32 ----
    const int m_off3 = (wid & 3) * 32;
    const int n_off3 = (wid >> 2) * 32;
    float o[2][4][4];
#pragma unroll
    for (int mt = 0; mt < 2; mt++)
#pragma unroll
        for (int nt = 0; nt < 4; nt++)
#pragma unroll
            for (int e = 0; e < 4; e++) o[mt][nt][e] = 0.f;

    // (a) (A_h + A_l) @ v_h : K-dim = 128
#pragma unroll
    for (int ks = 0; ks < 8; ks++) {
        const int jb = ks * 16;
        const int kcol = ks * 32;
        uint32_t bfh[2][4];
#pragma unroll
        for (int p = 0; p < 2; p++)
            ldmx4t(bfh[p], sb + OFF_VH + (jb + a_r) * QROWB + (n_off3 + p * 16 + a_c) * 2);
        uint32_t af[2][4];
#pragma unroll
        for (int mt = 0; mt < 2; mt++)
            ldmx4(af[mt], sb + OFF_AH + (m_off3 + mt * 16 + a_r) * AROWB + kcol + a_c * 2);
#pragma unroll
        for (int mt = 0; mt < 2; mt++)
#pragma unroll
            for (int nt = 0; nt < 4; nt++)
                mma_f16(o[mt][nt], af[mt], &bfh[nt >> 1][(nt & 1) * 2]);
#pragma unroll
        for (int mt = 0; mt < 2; mt++)
            ldmx4(af[mt], sb + OFF_AL + (m_off3 + mt * 16 + a_r) * AROWB + kcol + a_c * 2);
#pragma unroll
        for (int mt = 0; mt < 2; mt++)
#pragma unroll
            for (int nt = 0; nt < 4; nt++)
                mma_f16(o[mt][nt], af[mt], &bfh[nt >> 1][(nt & 1) * 2]);
    }

    // (b) (q_h + q_l) @ Sp_h : K-dim = 64
#pragma unroll
    for (int ks = 0; ks < 4; ks++) {
        const int db = ks * 16;
        const int kcol = ks * 32;
        uint32_t bfh[2][4];
#pragma unroll
        for (int p = 0; p < 2; p++)
            ldmx4t(bfh[p], sb + OFF_SPH + (db + a_r) * QROWB + (n_off3 + p * 16 + a_c) * 2);
        uint32_t af[2][4];
#pragma unroll
        for (int mt = 0; mt < 2; mt++)
            ldmx4(af[mt], sb + OFF_QH + (m_off3 + mt * 16 + a_r) * QROWB + kcol + a_c * 2);
#pragma unroll
        for (int mt = 0; mt < 2; mt++)
#pragma unroll
            for (int nt = 0; nt < 4; nt++)
                mma_f16(o[mt][nt], af[mt], &bfh[nt >> 1][(nt & 1) * 2]);
#pragma unroll
        for (int mt = 0; mt < 2; mt++)
            ldmx4(af[mt], sb + OFF_QL + (m_off3 + mt * 16 + a_r) * QROWB + kcol + a_c * 2);
#pragma unroll
        for (int mt = 0; mt < 2; mt++)
#pragma unroll
            for (int nt = 0; nt < 4; nt++)
                mma_f16(o[mt][nt], af[mt], &bfh[nt >> 1][(nt & 1) * 2]);
    }
    __syncthreads();   // den ready; QH reads done

    // ---- P4: divide by den, stage fp16 into (reused) QH region ----
#pragma unroll
    for (int mt = 0; mt < 2; mt++) {
        const int r0 = m_off3 + mt * 16 + gr;
        const int r1 = r0 + 8;
        const float i0 = 1.f / den[r0];
        const float i1 = 1.f / den[r1];
#pragma unroll
        for (int nt = 0; nt < 4; nt++) {
            const int col = n_off3 + nt * 8 + gc2;
            *(__half2*)(smem + OFF_QH + r0 * QROWB + col * 2) =
                __floats2half2_rn(o[mt][nt][0] * i0, o[mt][nt][1] * i0);
            *(__half2*)(smem + OFF_QH + r1 * QROWB + col * 2) =
                __floats2half2_rn(o[mt][nt][2] * i1, o[mt][nt][3] * i1);
        }
    }
    __syncthreads();

    // ---- P5: coalesced global writes ----
#pragma unroll
    for (int it = 0; it < 8; it++) {
        int idx = tid + it * 256;
        int r = idx >> 4, c4 = (idx & 15) * 4;
        uint2 vh = *(const uint2*)(smem + OFF_QH + r * QROWB + c4 * 2);
        *reinterpret_cast<uint2*>(Oh + base + (size_t)r * EMB + c4) = vh;
    }
}

// ---------------- launch ----------------
extern "C" void kernel_launch(void* const* d_in, const int* in_sizes, int n_in,
                              void* d_out, int out_size)
{
    const float* x  = (const float*)d_in[0];
    const float* Wq = (const float*)d_in[1];
    const float* Wk = (const float*)d_in[2];
    const float* Wv = (const float*)d_in[3];
    const float* Wo = (const float*)d_in[4];
    const float* bo = (const float*)d_in[5];
    float* out = (float*)d_out;
    (void)in_sizes; (void)n_in; (void)out_size;

    float *pS, *pSp, *pZ, *pZp;
    cudaGetSymbolAddress((void**)&pS,  g_S);
    cudaGetSymbolAddress((void**)&pSp, g_Sp);
    cudaGetSymbolAddress((void**)&pZ,  g_z);
    cudaGetSymbolAddress((void**)&pZp, g_zp);

    __half *xh, *qh_, *ql_, *kh_, *kl_, *vh_, *vl_, *ah, *wh;
    cudaGetSymbolAddress((void**)&xh,  g_xh);
    cudaGetSymbolAddress((void**)&qh_, g_qh);
    cudaGetSymbolAddress((void**)&ql_, g_ql);
    cudaGetSymbolAddress((void**)&kh_, g_kh);
    cudaGetSymbolAddress((void**)&kl_, g_kl);
    cudaGetSymbolAddress((void**)&vh_, g_vh);
    cudaGetSymbolAddress((void**)&vl_, g_vl);
    cudaGetSymbolAddress((void**)&ah,  g_ah);
    cudaGetSymbolAddress((void**)&wh,  g_w);

    cudaFuncSetAttribute(mma_gemm_half<0>,
                         cudaFuncAttributeMaxDynamicSharedMemorySize, GEMM_SMEM);
    cudaFuncSetAttribute(mma_gemm_half<1>,
                         cudaFuncAttributeMaxDynamicSharedMemorySize, GEMM_SMEM);
    cudaFuncSetAttribute(chunk_stats_tc,
                         cudaFuncAttributeMaxDynamicSharedMemorySize, CS_SMEM);
    cudaFuncSetAttribute(attn_mma_kernel,
                         cudaFuncAttributeMaxDynamicSharedMemorySize, ATTN_SMEM);

    const int n4x = MROWS * EMB / 4;   // 1048576
    const int n4w = EMB * EMB / 4;     // 262144

    // operand conversion
    conv_x_kernel<<<n4x / 256, 256>>>(x, xh, n4x);
    conv_w_kernel<<<dim3(n4w / 256, 4), 256>>>(Wq, Wk, Wv, Wo, wh);

    // Fused Q/K/V projections, 1-pass fp16 -> fp16 hi/lo outputs (phi for z<2)
    dim3 qkv_grid(EMB / 128, MROWS / 128, 3);     // (8, 32, 3)
    mma_gemm_half<0><<<qkv_grid, 256, GEMM_SMEM>>>(xh, wh, nullptr, nullptr,
                                                   qh_, ql_, kh_, kl_, vh_, vl_);

    // Chunked recurrent state: tc stats -> prefix -> tc output (emits fp16 hi)
    chunk_stats_tc<<<BATCH * NH * NC, 256, CS_SMEM>>>(kh_, kl_, vh_, vl_, pS, pZ);
    prefix_kernel<<<BATCH * NH, 256>>>(pS, pZ, pSp, pZp);
    attn_mma_kernel<<<BATCH * NH * NC, 256, ATTN_SMEM>>>(qh_, ql_, kh_, kl_, vh_,
                                                         pSp, pZp, ah);

    // Output projection + bias (1-pass, fp32 out)
    dim3 o_grid(EMB / 128, MROWS / 128, 1);
    mma_gemm_half<1><<<o_grid, 256, GEMM_SMEM>>>(ah, wh + (size_t)3 * EMB * EMB, bo,
                                                 out, nullptr, nullptr, nullptr,
                                                 nullptr, nullptr, nullptr);
}